// round 11
// baseline (speedup 1.0000x reference)
#include <cuda_runtime.h>
#include <cuda_bf16.h>
#include <math.h>
#include <float.h>
#include <stdint.h>

#define Bn   64
#define Tn   32
#define NEFc 256
#define Sn   289
#define SPAD 384
#define S2   320
#define Kq   16384
#define G1f  4.0f
#define G2f  5.0f
#define G3f  10.0f
#define INV_T 20.0f
#define EPSf 1e-8f

// ---------------- device scratch (bf16 single precision copies) ----------------
__device__ uint4 g_A4[64 * SPAD * 256 / 8];   // ctxT [j][s_pad][c] bf16
__device__ uint4 g_X4[64 * 256 * SPAD / 8];   // imgf [j][c][s_pad] bf16
__device__ uint4 g_B4[2048 * 256 / 8];        // we   [i*32+t][c] bf16
__device__ float g_qn[2048];
__device__ float g_codes[4][Bn * NEFc];
__device__ float g_simT[Bn * Bn];
__device__ float g_part[2][Bn][256][2];       // moco per-kblock (max, sumexp)
__device__ float g_small[2][Bn * Bn];

// ---------------- helpers ----------------
__device__ __forceinline__ uint32_t smem_u32(const void* p) {
    uint32_t a;
    asm("{ .reg .u64 t; cvta.to.shared.u64 t, %1; cvt.u32.u64 %0, t; }" : "=r"(a) : "l"(p));
    return a;
}
__device__ __forceinline__ void ldm_x4(uint32_t addr, uint32_t& r0, uint32_t& r1, uint32_t& r2, uint32_t& r3) {
    asm volatile("ldmatrix.sync.aligned.m8n8.x4.shared.b16 {%0,%1,%2,%3}, [%4];"
                 : "=r"(r0), "=r"(r1), "=r"(r2), "=r"(r3) : "r"(addr));
}
#define MMA16816(d, A0, A1, A2, A3, B0, B1)                                   \
    asm volatile("mma.sync.aligned.m16n8k16.row.col.f32.bf16.bf16.f32 "       \
                 "{%0,%1,%2,%3},{%4,%5,%6,%7},{%8,%9},{%0,%1,%2,%3};"          \
                 : "+f"((d)[0]), "+f"((d)[1]), "+f"((d)[2]), "+f"((d)[3])      \
                 : "r"(A0), "r"(A1), "r"(A2), "r"(A3), "r"(B0), "r"(B1))

__device__ __forceinline__ void cp16(uint32_t s, const void* g) {
    asm volatile("cp.async.ca.shared.global [%0], [%1], 16;" :: "r"(s), "l"(g));
}
#define CP_COMMIT() asm volatile("cp.async.commit_group;" ::: "memory")
#define CP_WAIT1()  asm volatile("cp.async.wait_group 1;" ::: "memory")
#define CP_WAIT0()  asm volatile("cp.async.wait_group 0;" ::: "memory")

// ---------------- prep_AX ----------------
#define PAX_SMEM (64 * 385 * 4)
__global__ void __launch_bounds__(256) prep_AX(const float* __restrict__ imgf) {
    const int j = blockIdx.x, ct = blockIdx.y;
    extern __shared__ float tile[];
    const int tid = threadIdx.x;
    const float* base = imgf + ((size_t)j * 256 + ct * 64) * Sn;
    for (int idx = tid; idx < 64 * Sn; idx += 256) {
        int r = idx / Sn, s = idx - r * Sn;
        tile[r * 385 + s] = base[(size_t)r * Sn + s];
    }
    __syncthreads();
    for (int idx = tid; idx < SPAD * 64; idx += 256) {
        const int s = idx >> 6, c = idx & 63;
        float v = (s < Sn) ? tile[c * 385 + s] : 0.f;
        ((__nv_bfloat16*)g_A4)[((size_t)j * SPAD + s) * 256 + ct * 64 + c] = __float2bfloat16(v);
    }
    for (int idx = tid; idx < 64 * S2; idx += 256) {
        const int c = idx / S2, s = idx - c * S2;
        float v = (s < Sn) ? tile[c * 385 + s] : 0.f;
        ((__nv_bfloat16*)g_X4)[((size_t)j * 256 + ct * 64 + c) * SPAD + s] = __float2bfloat16(v);
    }
}

__global__ void prep_B(const float* __restrict__ we) {
    int r = blockIdx.x, c = threadIdx.x;
    float v = we[(size_t)r * 256 + c];
    ((__nv_bfloat16*)g_B4)[(size_t)r * 256 + c] = __float2bfloat16(v);
    __shared__ float red[8];
    float s = v * v;
    for (int o = 16; o; o >>= 1) s += __shfl_down_sync(0xffffffffu, s, o);
    if ((c & 31) == 0) red[c >> 5] = s;
    __syncthreads();
    if (c == 0) {
        float tot = 0.f;
#pragma unroll
        for (int w = 0; w < 8; w++) tot += red[w];
        g_qn[r] = sqrtf(tot);
    }
}

__global__ void normalize_kernel(const float* __restrict__ c0, const float* __restrict__ c1,
                                 const float* __restrict__ c2, const float* __restrict__ c3) {
    int i = blockIdx.x;
    int m = blockIdx.y;
    const float* src = (m == 0) ? c0 : (m == 1) ? c1 : (m == 2) ? c2 : c3;
    int tid = threadIdx.x;
    __shared__ float red[8];
    float v = src[i * NEFc + tid];
    float s = v * v;
    for (int o = 16; o; o >>= 1) s += __shfl_down_sync(0xffffffffu, s, o);
    if ((tid & 31) == 0) red[tid >> 5] = s;
    __syncthreads();
    float tot = 0.f;
#pragma unroll
    for (int w = 0; w < 8; w++) tot += red[w];
    g_codes[m][i * NEFc + tid] = v / fmaxf(sqrtf(tot), EPSf);
}

// ---------------- word kernel smem layout (bytes) ----------------
#define OFF_SC   0          // scores 320x65 f32 = 83200
#define OFF_W    83200      // W 64x528 = 33792
#define OFF_AB0  116992     // A buf0 64x528
#define OFF_AB1  150784     // A buf1 -> end 184576
#define OFF_E    116992     // e 64x784 = 50176 (after phase1)
#define OFF_XB0  0          // X buf0 128x272 = 34816 (after epilogue)
#define OFF_XB1  34816
#define OFF_DEN  184576
#define OFF_NUM  184832
#define OFF_WN2  185088
#define OFF_RMAX 185344     // 2560
#define OFF_RINV 187904     // 2560
#define WK_SMEM  190464

__global__ void __launch_bounds__(256, 1) word_mma_kernel() {
    const int j  = blockIdx.x >> 5;
    const int ip = blockIdx.x & 31;
    extern __shared__ char sm[];
    const uint32_t sb = smem_u32(sm);
    const int tid = threadIdx.x, lane = tid & 31, w = tid >> 5;

    float* scp   = (float*)(sm + OFF_SC);
    float* denA  = (float*)(sm + OFF_DEN);
    float* numA  = (float*)(sm + OFF_NUM);
    float* wn2A  = (float*)(sm + OFF_WN2);
    float* rmaxp = (float*)(sm + OFF_RMAX);
    float* rinvp = (float*)(sm + OFF_RINV);
    if (tid < 192) denA[tid] = 0.f;

    // prologue: W and A chunk 0 (one group)
    for (int idx = tid; idx < 2048; idx += 256) {
        int r = idx >> 5, cb = idx & 31;
        cp16(sb + OFF_W + r * 528 + cb * 16, g_B4 + (((size_t)(ip * 64 + r)) << 5) + cb);
    }
    for (int idx = tid; idx < 2048; idx += 256) {
        int r = idx >> 5, cb = idx & 31;
        cp16(sb + OFF_AB0 + r * 528 + cb * 16, g_A4 + (((size_t)j * SPAD + r) << 5) + cb);
    }
    CP_COMMIT();

    // zero scores buffer (atomic accumulation target), overlapped with loads
    for (int k = tid; k < 320 * 65; k += 256) scp[k] = 0.f;

    const uint32_t rowA  = (lane & 7) + ((lane >> 3) & 1) * 8;
    const uint32_t coffA = (lane >> 4) * 16;
    const uint32_t boffB = ((lane >> 3) & 1) * 16;

    // ===== phase 1: 5 chunks of 64 s-rows; warps 2m x 2n x 2k; atomic score adds =====
    {
        const int wk  = w >> 2;
        const int wm1 = (w >> 1) & 1;
        const int wn1 = w & 1;
        const uint32_t bRow1 = 32u * wn1 + (((uint32_t)lane >> 4) << 3) + (lane & 7);

        for (int ch = 0; ch < 5; ch++) {
            if (ch + 1 < 5) {
                uint32_t dst = sb + ((ch + 1) & 1 ? OFF_AB1 : OFF_AB0);
                for (int idx = tid; idx < 2048; idx += 256) {
                    int r = idx >> 5, cb = idx & 31;
                    cp16(dst + r * 528 + cb * 16,
                         g_A4 + (((size_t)j * SPAD + (ch + 1) * 64 + r) << 5) + cb);
                }
                CP_COMMIT();
                CP_WAIT1();
            } else {
                CP_WAIT0();
            }
            __syncthreads();

            float acc[2][4][4];
#pragma unroll
            for (int mi = 0; mi < 2; mi++)
#pragma unroll
                for (int nf = 0; nf < 4; nf++)
#pragma unroll
                    for (int r = 0; r < 4; r++) acc[mi][nf][r] = 0.f;

            const uint32_t aB = sb + (ch & 1 ? OFF_AB1 : OFF_AB0)
                              + (wm1 * 32 + rowA) * 528 + coffA + (uint32_t)wk * 256u;
            const uint32_t bB = sb + OFF_W + bRow1 * 528 + boffB + (uint32_t)wk * 256u;

#pragma unroll
            for (int k = 0; k < 8; k++) {
                const uint32_t kb = (uint32_t)k * 32u;
                uint32_t a0, a1, a2, a3, a4, a5, a6, a7;
                uint32_t h0, h1, h2, h3, h4, h5, h6, h7;
                ldm_x4(aB + kb, a0, a1, a2, a3);
                ldm_x4(aB + 16 * 528 + kb, a4, a5, a6, a7);
                ldm_x4(bB + kb, h0, h1, h2, h3);
                ldm_x4(bB + 16 * 528 + kb, h4, h5, h6, h7);
                MMA16816(acc[0][0], a0, a1, a2, a3, h0, h1);
                MMA16816(acc[0][1], a0, a1, a2, a3, h2, h3);
                MMA16816(acc[0][2], a0, a1, a2, a3, h4, h5);
                MMA16816(acc[0][3], a0, a1, a2, a3, h6, h7);
                MMA16816(acc[1][0], a4, a5, a6, a7, h0, h1);
                MMA16816(acc[1][1], a4, a5, a6, a7, h2, h3);
                MMA16816(acc[1][2], a4, a5, a6, a7, h4, h5);
                MMA16816(acc[1][3], a4, a5, a6, a7, h6, h7);
            }
            __syncthreads();   // A buffer free for next prefetch

            // atomic accumulation of k-half partials (drained by phase-end barrier)
#pragma unroll
            for (int mi = 0; mi < 2; mi++) {
                const int row = ch * 64 + wm1 * 32 + mi * 16 + (lane >> 2);
#pragma unroll
                for (int nf = 0; nf < 4; nf++) {
                    const int col = wn1 * 32 + nf * 8 + (lane & 3) * 2;
                    atomicAdd(&scp[row * 65 + col],           acc[mi][nf][0]);
                    atomicAdd(&scp[row * 65 + col + 1],       acc[mi][nf][1]);
                    atomicAdd(&scp[(row + 8) * 65 + col],     acc[mi][nf][2]);
                    atomicAdd(&scp[(row + 8) * 65 + col + 1], acc[mi][nf][3]);
                }
            }
        }
    }
    __syncthreads();

    // ===== epilogue: softmaxes, den/num, e -> smem bf16 =====
    for (int r = tid; r < 320; r += 256) {
#pragma unroll
        for (int h = 0; h < 2; h++) {
            float m = -FLT_MAX;
            for (int t = 0; t < 32; t++) m = fmaxf(m, scp[r * 65 + h * 32 + t]);
            float s = 0.f;
            for (int t = 0; t < 32; t++) s += __expf(scp[r * 65 + h * 32 + t] - m);
            rmaxp[r * 2 + h] = m;
            rinvp[r * 2 + h] = 1.f / s;
        }
    }
    __syncthreads();
    {
        const int t = tid & 63, sg = tid >> 6, h = t >> 5;
        float dpart = 0.f, npart = 0.f;
        __nv_bfloat16* eP = (__nv_bfloat16*)(sm + OFF_E);
        for (int k2 = 0; k2 < 80; k2++) {
            const int s = sg * 80 + k2;   // covers s < 320
            float e = 0.f;
            if (s < Sn) {
                float sv = scp[s * 65 + t];
                float a1 = __expf(sv - rmaxp[s * 2 + h]) * rinvp[s * 2 + h];
                e = __expf(G1f * a1);
                dpart += e;
                npart += e * sv;
            }
            eP[t * 392 + s] = __float2bfloat16(e);
        }
        atomicAdd(&denA[t], dpart);
        atomicAdd(&numA[t], npart);
    }
    __syncthreads();   // scp consumed; X buffers may overwrite it

    // ===== phase 2: wC = X @ e^T; K = 320; chunks {128,128,64} x 2 m-tiles =====
    {
        const int wm2 = w >> 1;
        const int wn2 = w & 1;
        const uint32_t bRow2 = 32u * wn2 + (((uint32_t)lane >> 4) << 3) + (lane & 7);

        for (int idx = tid; idx < 2048; idx += 256) {
            int r = idx >> 4, cb = idx & 15;
            cp16(sb + OFF_XB0 + r * 272 + cb * 16, g_X4 + (((size_t)(j * 256 + r)) * 48) + cb);
        }
        CP_COMMIT();

        float acc2[2][4][4];
        for (int q = 0; q < 6; q++) {
            const int sc3 = q % 3;
            const uint32_t xb = sb + (q & 1 ? OFF_XB1 : OFF_XB0);
            if (q + 1 < 6) {
                const int mtn = (q + 1) / 3, sc3n = (q + 1) % 3;
                uint32_t dst = sb + ((q + 1) & 1 ? OFF_XB1 : OFF_XB0);
                if (sc3n < 2) {
                    for (int idx = tid; idx < 2048; idx += 256) {
                        int r = idx >> 4, cb = idx & 15;
                        cp16(dst + r * 272 + cb * 16,
                             g_X4 + (((size_t)(j * 256 + mtn * 128 + r)) * 48) + sc3n * 16 + cb);
                    }
                } else {
                    for (int idx = tid; idx < 1024; idx += 256) {
                        int r = idx >> 3, cb = idx & 7;
                        cp16(dst + r * 272 + cb * 16,
                             g_X4 + (((size_t)(j * 256 + mtn * 128 + r)) * 48) + 32 + cb);
                    }
                }
                CP_COMMIT();
                CP_WAIT1();
            } else {
                CP_WAIT0();
            }
            __syncthreads();

            if (sc3 == 0) {
#pragma unroll
                for (int mi = 0; mi < 2; mi++)
#pragma unroll
                    for (int n = 0; n < 4; n++)
#pragma unroll
                        for (int r = 0; r < 4; r++) acc2[mi][n][r] = 0.f;
            }

            const uint32_t eB0 = sb + OFF_E + bRow2 * 784 + (uint32_t)sc3 * 256u + boffB;
            const uint32_t eB1 = eB0 + 16 * 784;
            const uint32_t xA  = xb + (wm2 * 32 + rowA) * 272 + coffA;

            const int kmax = (sc3 == 2) ? 4 : 8;
#pragma unroll 4
            for (int k = 0; k < kmax; k++) {
                const uint32_t kb = (uint32_t)k * 32u;
                uint32_t x0, x1, x2, x3, x4, x5, x6, x7;
                uint32_t e0, e1, e2, e3, e4, e5, e6, e7;
                ldm_x4(xA + kb, x0, x1, x2, x3);
                ldm_x4(xA + 16 * 272 + kb, x4, x5, x6, x7);
                ldm_x4(eB0 + kb, e0, e1, e2, e3);
                ldm_x4(eB1 + kb, e4, e5, e6, e7);
                MMA16816(acc2[0][0], x0, x1, x2, x3, e0, e1);
                MMA16816(acc2[0][1], x0, x1, x2, x3, e2, e3);
                MMA16816(acc2[0][2], x0, x1, x2, x3, e4, e5);
                MMA16816(acc2[0][3], x0, x1, x2, x3, e6, e7);
                MMA16816(acc2[1][0], x4, x5, x6, x7, e0, e1);
                MMA16816(acc2[1][1], x4, x5, x6, x7, e2, e3);
                MMA16816(acc2[1][2], x4, x5, x6, x7, e4, e5);
                MMA16816(acc2[1][3], x4, x5, x6, x7, e6, e7);
            }
            __syncthreads();   // xb fully consumed

            if (sc3 == 2) {
#pragma unroll
                for (int n = 0; n < 4; n++) {
                    float v0 = 0.f, v1 = 0.f;
#pragma unroll
                    for (int mi = 0; mi < 2; mi++) {
                        v0 += acc2[mi][n][0] * acc2[mi][n][0] + acc2[mi][n][2] * acc2[mi][n][2];
                        v1 += acc2[mi][n][1] * acc2[mi][n][1] + acc2[mi][n][3] * acc2[mi][n][3];
                    }
#pragma unroll
                    for (int o = 4; o <= 16; o <<= 1) {
                        v0 += __shfl_xor_sync(0xffffffffu, v0, o);
                        v1 += __shfl_xor_sync(0xffffffffu, v1, o);
                    }
                    if (lane < 4) {
                        const int t = (4 * wn2 + n) * 8 + lane * 2;
                        atomicAdd(&wn2A[t], v0);
                        atomicAdd(&wn2A[t + 1], v1);
                    }
                }
            }
        }
    }
    __syncthreads();

    if (tid < 64) {
        const int t = tid;
        float dinv = 1.f / denA[t];
        float wnv = sqrtf(wn2A[t]) * dinv;
        float nm = numA[t] * dinv;
        float qnv = g_qn[ip * 64 + t];
        float cosv = nm / fmaxf(qnv * wnv, EPSf);
        float v = G2f * cosv;
        float m = v;
        for (int o = 16; o; o >>= 1) m = fmaxf(m, __shfl_xor_sync(0xffffffffu, m, o));
        float e = __expf(v - m);
        for (int o = 16; o; o >>= 1) e += __shfl_xor_sync(0xffffffffu, e, o);
        if (lane == 0) g_simT[j * 64 + ip * 2 + (tid >> 5)] = logf(e) + m;
    }
}

// ---------------- moco GEMM with fused per-block LSE ----------------
__global__ void __launch_bounds__(256) moco_gemm_kernel(const float* __restrict__ queue,
                                                        const float* __restrict__ queue_im) {
    int k0 = blockIdx.x * 64;
    int d = blockIdx.y;
    const float* A = g_codes[d];
    const float* Q = (d == 0) ? queue : queue_im;
    __shared__ float sA[64 * 33];
    __shared__ float sB[32 * 65];
    int tid = threadIdx.x;
    int rg = tid >> 4;
    int kg = tid & 15;
    float acc[4][4];
#pragma unroll
    for (int u = 0; u < 4; u++)
#pragma unroll
        for (int v = 0; v < 4; v++) acc[u][v] = 0.f;
    for (int c0 = 0; c0 < NEFc; c0 += 32) {
        __syncthreads();
        for (int idx = tid; idx < 64 * 32; idx += 256) {
            int r = idx >> 5, cc = idx & 31;
            sA[r * 33 + cc] = A[r * NEFc + c0 + cc];
        }
        for (int idx = tid; idx < 32 * 64; idx += 256) {
            int cc = idx >> 6, kk = idx & 63;
            sB[cc * 65 + kk] = Q[(size_t)(c0 + cc) * Kq + k0 + kk];
        }
        __syncthreads();
#pragma unroll 4
        for (int cc = 0; cc < 32; cc++) {
            float a0 = sA[(rg * 4 + 0) * 33 + cc];
            float a1 = sA[(rg * 4 + 1) * 33 + cc];
            float a2 = sA[(rg * 4 + 2) * 33 + cc];
            float a3 = sA[(rg * 4 + 3) * 33 + cc];
#pragma unroll
            for (int v = 0; v < 4; v++) {
                float b = sB[cc * 65 + kg + 16 * v];
                acc[0][v] += a0 * b;
                acc[1][v] += a1 * b;
                acc[2][v] += a2 * b;
                acc[3][v] += a3 * b;
            }
        }
    }
#pragma unroll
    for (int u = 0; u < 4; u++) {
        float z0 = acc[u][0] * INV_T, z1 = acc[u][1] * INV_T;
        float z2 = acc[u][2] * INV_T, z3 = acc[u][3] * INV_T;
        float m = fmaxf(fmaxf(z0, z1), fmaxf(z2, z3));
        float s = __expf(z0 - m) + __expf(z1 - m) + __expf(z2 - m) + __expf(z3 - m);
#pragma unroll
        for (int o = 1; o < 16; o <<= 1) {
            float om = __shfl_xor_sync(0xffffffffu, m, o);
            float os = __shfl_xor_sync(0xffffffffu, s, o);
            float nm = fmaxf(m, om);
            s = s * __expf(m - nm) + os * __expf(om - nm);
            m = nm;
        }
        if (kg == 0) {
            g_part[d][rg * 4 + u][blockIdx.x][0] = m;
            g_part[d][rg * 4 + u][blockIdx.x][1] = s;
        }
    }
}

#define K5_SMEM (2 * 64 * 257 * 4)
__global__ void __launch_bounds__(256) pair_gemm_kernel() {
    int d = blockIdx.x;
    const float* A  = g_codes[(d == 0) ? 0 : 1];
    const float* Bm = g_codes[(d == 0) ? 1 : 3];
    extern __shared__ float sh2[];
    float* shA = sh2;
    float* shB = sh2 + 64 * 257;
    int tid = threadIdx.x;
    for (int idx = tid; idx < 64 * 256; idx += 256) {
        int r = idx >> 8, c = idx & 255;
        shA[r * 257 + c] = A[idx];
        shB[r * 257 + c] = Bm[idx];
    }
    __syncthreads();
    int rg = tid >> 4, cg = tid & 15;
    float acc[4][4];
#pragma unroll
    for (int u = 0; u < 4; u++)
#pragma unroll
        for (int v = 0; v < 4; v++) acc[u][v] = 0.f;
#pragma unroll 4
    for (int k = 0; k < 256; k++) {
        float a0 = shA[(rg * 4 + 0) * 257 + k];
        float a1 = shA[(rg * 4 + 1) * 257 + k];
        float a2 = shA[(rg * 4 + 2) * 257 + k];
        float a3 = shA[(rg * 4 + 3) * 257 + k];
        float b0 = shB[(cg * 4 + 0) * 257 + k];
        float b1 = shB[(cg * 4 + 1) * 257 + k];
        float b2 = shB[(cg * 4 + 2) * 257 + k];
        float b3 = shB[(cg * 4 + 3) * 257 + k];
        acc[0][0] += a0 * b0; acc[0][1] += a0 * b1; acc[0][2] += a0 * b2; acc[0][3] += a0 * b3;
        acc[1][0] += a1 * b0; acc[1][1] += a1 * b1; acc[1][2] += a1 * b2; acc[1][3] += a1 * b3;
        acc[2][0] += a2 * b0; acc[2][1] += a2 * b1; acc[2][2] += a2 * b2; acc[2][3] += a2 * b3;
        acc[3][0] += a3 * b0; acc[3][1] += a3 * b1; acc[3][2] += a3 * b2; acc[3][3] += a3 * b3;
    }
#pragma unroll
    for (int u = 0; u < 4; u++)
#pragma unroll
        for (int v = 0; v < 4; v++)
            g_small[d][(rg * 4 + u) * 64 + cg * 4 + v] = G3f * acc[u][v];
}

__device__ float lse_md_row(const float* M, int r, float scale) {
    float mx = -FLT_MAX;
    for (int c2 = 0; c2 < 64; c2++) mx = fmaxf(mx, scale * M[r * 64 + c2]);
    float s = 0.f;
    for (int c2 = 0; c2 < 64; c2++) s += __expf(scale * M[r * 64 + c2] - mx);
    return logf(s) + mx - scale * M[r * 64 + r];
}
__device__ float lse_md_col(const float* M, int c2, float scale) {
    float mx = -FLT_MAX;
    for (int r = 0; r < 64; r++) mx = fmaxf(mx, scale * M[r * 64 + c2]);
    float s = 0.f;
    for (int r = 0; r < 64; r++) s += __expf(scale * M[r * 64 + c2] - mx);
    return logf(s) + mx - scale * M[c2 * 64 + c2];
}

__global__ void finalize_kernel(float* __restrict__ out) {
    __shared__ float sv[8][64];
    int tid = threadIdx.x;
    if (tid < 128) {
        const int d = tid >> 6, i = tid & 63;
        float M = -FLT_MAX, S = 0.f;
        for (int b = 0; b < 256; b++) {
            float m = g_part[d][i][b][0], s = g_part[d][i][b][1];
            float nm = fmaxf(M, m);
            S = S * __expf(M - nm) + s * __expf(m - nm);
            M = nm;
        }
        float pos = 0.f;
        const float* a = g_codes[d];
        const float* b2 = g_codes[(d == 0) ? 3 : 2];
        for (int k = 0; k < NEFc; k++) pos += a[i * NEFc + k] * b2[i * NEFc + k];
        pos *= INV_T;
        float Mf = fmaxf(pos, M);
        float Sf = __expf(pos - Mf) + S * __expf(M - Mf);
        sv[6 + d][i] = logf(Sf) + Mf - pos;
    }
    __syncthreads();
    if (tid < 64) {
        int i = tid;
        sv[0][i] = lse_md_row(g_simT, i, G3f);
        sv[1][i] = lse_md_col(g_simT, i, G3f);
        sv[2][i] = lse_md_row(g_small[0], i, 1.f);
        sv[3][i] = lse_md_col(g_small[0], i, 1.f);
        sv[4][i] = lse_md_row(g_small[1], i, 1.f);
        sv[5][i] = lse_md_col(g_small[1], i, 1.f);
    }
    __syncthreads();
    if (tid == 0) {
        float a[8];
        for (int q2 = 0; q2 < 8; q2++) {
            float s = 0.f;
            for (int k = 0; k < 64; k++) s += sv[q2][k];
            a[q2] = s * (1.f / 64.f);
        }
        out[0] = a[0];
        out[1] = a[1];
        out[2] = a[2];
        out[3] = a[3];
        out[4] = 0.5f * (a[6] + a[7]);
        out[5] = a[4];
        out[6] = a[5];
    }
}

extern "C" void kernel_launch(void* const* d_in, const int* in_sizes, int n_in,
                              void* d_out, int out_size) {
    const float* cnn      = (const float*)d_in[0];
    const float* rnn      = (const float*)d_in[1];
    const float* imgf     = (const float*)d_in[2];
    const float* we       = (const float*)d_in[3];
    const float* cnn_aug  = (const float*)d_in[4];
    const float* rnn_aug  = (const float*)d_in[5];
    const float* queue    = (const float*)d_in[6];
    const float* queue_im = (const float*)d_in[7];
    float* out = (float*)d_out;

    cudaFuncSetAttribute(prep_AX, cudaFuncAttributeMaxDynamicSharedMemorySize, PAX_SMEM);
    cudaFuncSetAttribute(word_mma_kernel, cudaFuncAttributeMaxDynamicSharedMemorySize, WK_SMEM);
    cudaFuncSetAttribute(pair_gemm_kernel, cudaFuncAttributeMaxDynamicSharedMemorySize, K5_SMEM);

    prep_AX<<<dim3(64, 4), 256, PAX_SMEM>>>(imgf);                       // 1
    prep_B<<<2048, 256>>>(we);                                           // 2
    normalize_kernel<<<dim3(64, 4), 256>>>(cnn, rnn, cnn_aug, rnn_aug);  // 3
    word_mma_kernel<<<2048, 256, WK_SMEM>>>();                           // 4  <- ncu capture slot
    moco_gemm_kernel<<<dim3(256, 2), 256>>>(queue, queue_im);            // 5
    pair_gemm_kernel<<<2, 256, K5_SMEM>>>();                             // 6
    finalize_kernel<<<1, 256>>>(out);                                    // 7
}

// round 12
// speedup vs baseline: 1.1620x; 1.1620x over previous
#include <cuda_runtime.h>
#include <cuda_bf16.h>
#include <math.h>
#include <float.h>
#include <stdint.h>

#define Bn   64
#define Tn   32
#define NEFc 256
#define Sn   289
#define SPAD 384
#define S2   320
#define Kq   16384
#define G1f  4.0f
#define G2f  5.0f
#define G3f  10.0f
#define INV_T 20.0f
#define EPSf 1e-8f

// ---------------- device scratch (bf16 single precision copies) ----------------
__device__ uint4 g_A4[64 * SPAD * 256 / 8];   // ctxT [j][s_pad][c] bf16
__device__ uint4 g_X4[64 * 256 * SPAD / 8];   // imgf [j][c][s_pad] bf16
__device__ uint4 g_B4[2048 * 256 / 8];        // we   [i*32+t][c] bf16
__device__ float g_qn[2048];
__device__ float g_codes[4][Bn * NEFc];
__device__ float g_simT[Bn * Bn];
__device__ float g_part[2][Bn][256][2];       // moco per-kblock (max, sumexp)
__device__ float g_small[2][Bn * Bn];

// ---------------- helpers ----------------
__device__ __forceinline__ uint32_t smem_u32(const void* p) {
    uint32_t a;
    asm("{ .reg .u64 t; cvta.to.shared.u64 t, %1; cvt.u32.u64 %0, t; }" : "=r"(a) : "l"(p));
    return a;
}
__device__ __forceinline__ void ldm_x4(uint32_t addr, uint32_t& r0, uint32_t& r1, uint32_t& r2, uint32_t& r3) {
    asm volatile("ldmatrix.sync.aligned.m8n8.x4.shared.b16 {%0,%1,%2,%3}, [%4];"
                 : "=r"(r0), "=r"(r1), "=r"(r2), "=r"(r3) : "r"(addr));
}
#define MMA16816(d, A0, A1, A2, A3, B0, B1)                                   \
    asm volatile("mma.sync.aligned.m16n8k16.row.col.f32.bf16.bf16.f32 "       \
                 "{%0,%1,%2,%3},{%4,%5,%6,%7},{%8,%9},{%0,%1,%2,%3};"          \
                 : "+f"((d)[0]), "+f"((d)[1]), "+f"((d)[2]), "+f"((d)[3])      \
                 : "r"(A0), "r"(A1), "r"(A2), "r"(A3), "r"(B0), "r"(B1))

__device__ __forceinline__ void cp16(uint32_t s, const void* g) {
    asm volatile("cp.async.ca.shared.global [%0], [%1], 16;" :: "r"(s), "l"(g));
}
#define CP_COMMIT() asm volatile("cp.async.commit_group;" ::: "memory")
#define CP_WAIT1()  asm volatile("cp.async.wait_group 1;" ::: "memory")
#define CP_WAIT0()  asm volatile("cp.async.wait_group 0;" ::: "memory")

// ---------------- prep_AX ----------------
#define PAX_SMEM (64 * 385 * 4)
__global__ void __launch_bounds__(256) prep_AX(const float* __restrict__ imgf) {
    const int j = blockIdx.x, ct = blockIdx.y;
    extern __shared__ float tile[];
    const int tid = threadIdx.x;
    const float* base = imgf + ((size_t)j * 256 + ct * 64) * Sn;
    for (int idx = tid; idx < 64 * Sn; idx += 256) {
        int r = idx / Sn, s = idx - r * Sn;
        tile[r * 385 + s] = base[(size_t)r * Sn + s];
    }
    __syncthreads();
    for (int idx = tid; idx < SPAD * 64; idx += 256) {
        const int s = idx >> 6, c = idx & 63;
        float v = (s < Sn) ? tile[c * 385 + s] : 0.f;
        ((__nv_bfloat16*)g_A4)[((size_t)j * SPAD + s) * 256 + ct * 64 + c] = __float2bfloat16(v);
    }
    for (int idx = tid; idx < 64 * S2; idx += 256) {
        const int c = idx / S2, s = idx - c * S2;
        float v = (s < Sn) ? tile[c * 385 + s] : 0.f;
        ((__nv_bfloat16*)g_X4)[((size_t)j * 256 + ct * 64 + c) * SPAD + s] = __float2bfloat16(v);
    }
}

__global__ void prep_B(const float* __restrict__ we) {
    int r = blockIdx.x, c = threadIdx.x;
    float v = we[(size_t)r * 256 + c];
    ((__nv_bfloat16*)g_B4)[(size_t)r * 256 + c] = __float2bfloat16(v);
    __shared__ float red[8];
    float s = v * v;
    for (int o = 16; o; o >>= 1) s += __shfl_down_sync(0xffffffffu, s, o);
    if ((c & 31) == 0) red[c >> 5] = s;
    __syncthreads();
    if (c == 0) {
        float tot = 0.f;
#pragma unroll
        for (int w = 0; w < 8; w++) tot += red[w];
        g_qn[r] = sqrtf(tot);
    }
}

__global__ void normalize_kernel(const float* __restrict__ c0, const float* __restrict__ c1,
                                 const float* __restrict__ c2, const float* __restrict__ c3) {
    int i = blockIdx.x;
    int m = blockIdx.y;
    const float* src = (m == 0) ? c0 : (m == 1) ? c1 : (m == 2) ? c2 : c3;
    int tid = threadIdx.x;
    __shared__ float red[8];
    float v = src[i * NEFc + tid];
    float s = v * v;
    for (int o = 16; o; o >>= 1) s += __shfl_down_sync(0xffffffffu, s, o);
    if ((tid & 31) == 0) red[tid >> 5] = s;
    __syncthreads();
    float tot = 0.f;
#pragma unroll
    for (int w = 0; w < 8; w++) tot += red[w];
    g_codes[m][i * NEFc + tid] = v / fmaxf(sqrtf(tot), EPSf);
}

// ---------------- word kernel smem layout (bytes) ----------------
#define OFF_SC   0          // scores 320x65 f32 = 83200
#define OFF_W    83200      // W 64x528 = 33792
#define OFF_AB0  116992     // A buf0 64x528
#define OFF_AB1  150784     // A buf1 -> end 184576
#define OFF_E    116992     // e 64x784 = 50176 (after phase1)
#define OFF_XB0  0          // X buf0 128x272 = 34816 (after epilogue)
#define OFF_XB1  34816
#define OFF_DEN  184576
#define OFF_NUM  184832
#define OFF_WN2  185088
#define OFF_RMAX 185344     // 2560
#define OFF_RINV 187904     // 2560
#define WK_SMEM  190464

__global__ void __launch_bounds__(256, 1) word_mma_kernel() {
    const int j  = blockIdx.x >> 5;
    const int ip = blockIdx.x & 31;
    extern __shared__ char sm[];
    const uint32_t sb = smem_u32(sm);
    const int tid = threadIdx.x, lane = tid & 31, w = tid >> 5;

    float* scp   = (float*)(sm + OFF_SC);
    float* denA  = (float*)(sm + OFF_DEN);
    float* numA  = (float*)(sm + OFF_NUM);
    float* wn2A  = (float*)(sm + OFF_WN2);
    float* rmaxp = (float*)(sm + OFF_RMAX);
    float* rinvp = (float*)(sm + OFF_RINV);
    if (tid < 192) denA[tid] = 0.f;

    // prologue: W and A chunk 0 (one group)
    for (int idx = tid; idx < 2048; idx += 256) {
        int r = idx >> 5, cb = idx & 31;
        cp16(sb + OFF_W + r * 528 + cb * 16, g_B4 + (((size_t)(ip * 64 + r)) << 5) + cb);
    }
    for (int idx = tid; idx < 2048; idx += 256) {
        int r = idx >> 5, cb = idx & 31;
        cp16(sb + OFF_AB0 + r * 528 + cb * 16, g_A4 + (((size_t)j * SPAD + r) << 5) + cb);
    }
    CP_COMMIT();

    const uint32_t rowA  = (lane & 7) + ((lane >> 3) & 1) * 8;
    const uint32_t coffA = (lane >> 4) * 16;
    const uint32_t boffB = ((lane >> 3) & 1) * 16;

    // ===== phase 1: 5 chunks of 64 s-rows; warps 2m x 2n x 2k; store+merge (R10) =====
    {
        const int wk  = w >> 2;
        const int wm1 = (w >> 1) & 1;
        const int wn1 = w & 1;
        const uint32_t bRow1 = 32u * wn1 + (((uint32_t)lane >> 4) << 3) + (lane & 7);

        for (int ch = 0; ch < 5; ch++) {
            if (ch + 1 < 5) {
                uint32_t dst = sb + ((ch + 1) & 1 ? OFF_AB1 : OFF_AB0);
                for (int idx = tid; idx < 2048; idx += 256) {
                    int r = idx >> 5, cb = idx & 31;
                    cp16(dst + r * 528 + cb * 16,
                         g_A4 + (((size_t)j * SPAD + (ch + 1) * 64 + r) << 5) + cb);
                }
                CP_COMMIT();
                CP_WAIT1();
            } else {
                CP_WAIT0();
            }
            __syncthreads();

            float acc[2][4][4];
#pragma unroll
            for (int mi = 0; mi < 2; mi++)
#pragma unroll
                for (int nf = 0; nf < 4; nf++)
#pragma unroll
                    for (int r = 0; r < 4; r++) acc[mi][nf][r] = 0.f;

            const uint32_t aB = sb + (ch & 1 ? OFF_AB1 : OFF_AB0)
                              + (wm1 * 32 + rowA) * 528 + coffA + (uint32_t)wk * 256u;
            const uint32_t bB = sb + OFF_W + bRow1 * 528 + boffB + (uint32_t)wk * 256u;

#pragma unroll
            for (int k = 0; k < 8; k++) {
                const uint32_t kb = (uint32_t)k * 32u;
                uint32_t a0, a1, a2, a3, a4, a5, a6, a7;
                uint32_t h0, h1, h2, h3, h4, h5, h6, h7;
                ldm_x4(aB + kb, a0, a1, a2, a3);
                ldm_x4(aB + 16 * 528 + kb, a4, a5, a6, a7);
                ldm_x4(bB + kb, h0, h1, h2, h3);
                ldm_x4(bB + 16 * 528 + kb, h4, h5, h6, h7);
                MMA16816(acc[0][0], a0, a1, a2, a3, h0, h1);
                MMA16816(acc[0][1], a0, a1, a2, a3, h2, h3);
                MMA16816(acc[0][2], a0, a1, a2, a3, h4, h5);
                MMA16816(acc[0][3], a0, a1, a2, a3, h6, h7);
                MMA16816(acc[1][0], a4, a5, a6, a7, h0, h1);
                MMA16816(acc[1][1], a4, a5, a6, a7, h2, h3);
                MMA16816(acc[1][2], a4, a5, a6, a7, h4, h5);
                MMA16816(acc[1][3], a4, a5, a6, a7, h6, h7);
            }
            __syncthreads();   // all ldmatrix of chunk done

            if (wk == 0) {
#pragma unroll
                for (int mi = 0; mi < 2; mi++) {
                    const int row = ch * 64 + wm1 * 32 + mi * 16 + (lane >> 2);
#pragma unroll
                    for (int nf = 0; nf < 4; nf++) {
                        const int col = wn1 * 32 + nf * 8 + (lane & 3) * 2;
                        scp[row * 65 + col]           = acc[mi][nf][0];
                        scp[row * 65 + col + 1]       = acc[mi][nf][1];
                        scp[(row + 8) * 65 + col]     = acc[mi][nf][2];
                        scp[(row + 8) * 65 + col + 1] = acc[mi][nf][3];
                    }
                }
            }
            __syncthreads();
            if (wk == 1) {
#pragma unroll
                for (int mi = 0; mi < 2; mi++) {
                    const int row = ch * 64 + wm1 * 32 + mi * 16 + (lane >> 2);
#pragma unroll
                    for (int nf = 0; nf < 4; nf++) {
                        const int col = wn1 * 32 + nf * 8 + (lane & 3) * 2;
                        scp[row * 65 + col]           += acc[mi][nf][0];
                        scp[row * 65 + col + 1]       += acc[mi][nf][1];
                        scp[(row + 8) * 65 + col]     += acc[mi][nf][2];
                        scp[(row + 8) * 65 + col + 1] += acc[mi][nf][3];
                    }
                }
            }
        }
    }
    __syncthreads();

    // ===== epilogue: softmaxes, den/num, e -> smem bf16 (s < 320) =====
    for (int r = tid; r < 320; r += 256) {
#pragma unroll
        for (int h = 0; h < 2; h++) {
            float m = -FLT_MAX;
            for (int t = 0; t < 32; t++) m = fmaxf(m, scp[r * 65 + h * 32 + t]);
            float s = 0.f;
            for (int t = 0; t < 32; t++) s += __expf(scp[r * 65 + h * 32 + t] - m);
            rmaxp[r * 2 + h] = m;
            rinvp[r * 2 + h] = 1.f / s;
        }
    }
    __syncthreads();
    {
        const int t = tid & 63, sg = tid >> 6, h = t >> 5;
        float dpart = 0.f, npart = 0.f;
        __nv_bfloat16* eP = (__nv_bfloat16*)(sm + OFF_E);
        for (int k2 = 0; k2 < 80; k2++) {
            const int s = sg * 80 + k2;
            float e = 0.f;
            if (s < Sn) {
                float sv = scp[s * 65 + t];
                float a1 = __expf(sv - rmaxp[s * 2 + h]) * rinvp[s * 2 + h];
                e = __expf(G1f * a1);
                dpart += e;
                npart += e * sv;
            }
            eP[t * 392 + s] = __float2bfloat16(e);
        }
        atomicAdd(&denA[t], dpart);
        atomicAdd(&numA[t], npart);
    }
    __syncthreads();   // scp consumed; X buffers may overwrite it

    // ===== phase 2: wC = X @ e^T; K = 320; chunks {128,128,64} x 2 m-tiles =====
    {
        const int wm2 = w >> 1;
        const int wn2 = w & 1;
        const uint32_t bRow2 = 32u * wn2 + (((uint32_t)lane >> 4) << 3) + (lane & 7);

        for (int idx = tid; idx < 2048; idx += 256) {
            int r = idx >> 4, cb = idx & 15;
            cp16(sb + OFF_XB0 + r * 272 + cb * 16, g_X4 + (((size_t)(j * 256 + r)) * 48) + cb);
        }
        CP_COMMIT();

        float acc2[2][4][4];
        for (int q = 0; q < 6; q++) {
            const int sc3 = q % 3;
            const uint32_t xb = sb + (q & 1 ? OFF_XB1 : OFF_XB0);
            if (q + 1 < 6) {
                const int mtn = (q + 1) / 3, sc3n = (q + 1) % 3;
                uint32_t dst = sb + ((q + 1) & 1 ? OFF_XB1 : OFF_XB0);
                if (sc3n < 2) {
                    for (int idx = tid; idx < 2048; idx += 256) {
                        int r = idx >> 4, cb = idx & 15;
                        cp16(dst + r * 272 + cb * 16,
                             g_X4 + (((size_t)(j * 256 + mtn * 128 + r)) * 48) + sc3n * 16 + cb);
                    }
                } else {
                    for (int idx = tid; idx < 1024; idx += 256) {
                        int r = idx >> 3, cb = idx & 7;
                        cp16(dst + r * 272 + cb * 16,
                             g_X4 + (((size_t)(j * 256 + mtn * 128 + r)) * 48) + 32 + cb);
                    }
                }
                CP_COMMIT();
                CP_WAIT1();
            } else {
                CP_WAIT0();
            }
            __syncthreads();

            if (sc3 == 0) {
#pragma unroll
                for (int mi = 0; mi < 2; mi++)
#pragma unroll
                    for (int n = 0; n < 4; n++)
#pragma unroll
                        for (int r = 0; r < 4; r++) acc2[mi][n][r] = 0.f;
            }

            const uint32_t eB0 = sb + OFF_E + bRow2 * 784 + (uint32_t)sc3 * 256u + boffB;
            const uint32_t eB1 = eB0 + 16 * 784;
            const uint32_t xA  = xb + (wm2 * 32 + rowA) * 272 + coffA;

            const int kmax = (sc3 == 2) ? 4 : 8;
#pragma unroll 4
            for (int k = 0; k < kmax; k++) {
                const uint32_t kb = (uint32_t)k * 32u;
                uint32_t x0, x1, x2, x3, x4, x5, x6, x7;
                uint32_t e0, e1, e2, e3, e4, e5, e6, e7;
                ldm_x4(xA + kb, x0, x1, x2, x3);
                ldm_x4(xA + 16 * 272 + kb, x4, x5, x6, x7);
                ldm_x4(eB0 + kb, e0, e1, e2, e3);
                ldm_x4(eB1 + kb, e4, e5, e6, e7);
                MMA16816(acc2[0][0], x0, x1, x2, x3, e0, e1);
                MMA16816(acc2[0][1], x0, x1, x2, x3, e2, e3);
                MMA16816(acc2[0][2], x0, x1, x2, x3, e4, e5);
                MMA16816(acc2[0][3], x0, x1, x2, x3, e6, e7);
                MMA16816(acc2[1][0], x4, x5, x6, x7, e0, e1);
                MMA16816(acc2[1][1], x4, x5, x6, x7, e2, e3);
                MMA16816(acc2[1][2], x4, x5, x6, x7, e4, e5);
                MMA16816(acc2[1][3], x4, x5, x6, x7, e6, e7);
            }
            __syncthreads();   // xb fully consumed

            if (sc3 == 2) {
#pragma unroll
                for (int n = 0; n < 4; n++) {
                    float v0 = 0.f, v1 = 0.f;
#pragma unroll
                    for (int mi = 0; mi < 2; mi++) {
                        v0 += acc2[mi][n][0] * acc2[mi][n][0] + acc2[mi][n][2] * acc2[mi][n][2];
                        v1 += acc2[mi][n][1] * acc2[mi][n][1] + acc2[mi][n][3] * acc2[mi][n][3];
                    }
#pragma unroll
                    for (int o = 4; o <= 16; o <<= 1) {
                        v0 += __shfl_xor_sync(0xffffffffu, v0, o);
                        v1 += __shfl_xor_sync(0xffffffffu, v1, o);
                    }
                    if (lane < 4) {
                        const int t = (4 * wn2 + n) * 8 + lane * 2;
                        atomicAdd(&wn2A[t], v0);
                        atomicAdd(&wn2A[t + 1], v1);
                    }
                }
            }
        }
    }
    __syncthreads();

    if (tid < 64) {
        const int t = tid;
        float dinv = 1.f / denA[t];
        float wnv = sqrtf(wn2A[t]) * dinv;
        float nm = numA[t] * dinv;
        float qnv = g_qn[ip * 64 + t];
        float cosv = nm / fmaxf(qnv * wnv, EPSf);
        float v = G2f * cosv;
        float m = v;
        for (int o = 16; o; o >>= 1) m = fmaxf(m, __shfl_xor_sync(0xffffffffu, m, o));
        float e = __expf(v - m);
        for (int o = 16; o; o >>= 1) e += __shfl_xor_sync(0xffffffffu, e, o);
        if (lane == 0) g_simT[j * 64 + ip * 2 + (tid >> 5)] = logf(e) + m;
    }
}

// ---------------- moco GEMM with fused per-block LSE ----------------
__global__ void __launch_bounds__(256) moco_gemm_kernel(const float* __restrict__ queue,
                                                        const float* __restrict__ queue_im) {
    int k0 = blockIdx.x * 64;
    int d = blockIdx.y;
    const float* A = g_codes[d];
    const float* Q = (d == 0) ? queue : queue_im;
    __shared__ float sA[64 * 33];
    __shared__ float sB[32 * 65];
    int tid = threadIdx.x;
    int rg = tid >> 4;
    int kg = tid & 15;
    float acc[4][4];
#pragma unroll
    for (int u = 0; u < 4; u++)
#pragma unroll
        for (int v = 0; v < 4; v++) acc[u][v] = 0.f;
    for (int c0 = 0; c0 < NEFc; c0 += 32) {
        __syncthreads();
        for (int idx = tid; idx < 64 * 32; idx += 256) {
            int r = idx >> 5, cc = idx & 31;
            sA[r * 33 + cc] = A[r * NEFc + c0 + cc];
        }
        for (int idx = tid; idx < 32 * 64; idx += 256) {
            int cc = idx >> 6, kk = idx & 63;
            sB[cc * 65 + kk] = Q[(size_t)(c0 + cc) * Kq + k0 + kk];
        }
        __syncthreads();
#pragma unroll 4
        for (int cc = 0; cc < 32; cc++) {
            float a0 = sA[(rg * 4 + 0) * 33 + cc];
            float a1 = sA[(rg * 4 + 1) * 33 + cc];
            float a2 = sA[(rg * 4 + 2) * 33 + cc];
            float a3 = sA[(rg * 4 + 3) * 33 + cc];
#pragma unroll
            for (int v = 0; v < 4; v++) {
                float b = sB[cc * 65 + kg + 16 * v];
                acc[0][v] += a0 * b;
                acc[1][v] += a1 * b;
                acc[2][v] += a2 * b;
                acc[3][v] += a3 * b;
            }
        }
    }
#pragma unroll
    for (int u = 0; u < 4; u++) {
        float z0 = acc[u][0] * INV_T, z1 = acc[u][1] * INV_T;
        float z2 = acc[u][2] * INV_T, z3 = acc[u][3] * INV_T;
        float m = fmaxf(fmaxf(z0, z1), fmaxf(z2, z3));
        float s = __expf(z0 - m) + __expf(z1 - m) + __expf(z2 - m) + __expf(z3 - m);
#pragma unroll
        for (int o = 1; o < 16; o <<= 1) {
            float om = __shfl_xor_sync(0xffffffffu, m, o);
            float os = __shfl_xor_sync(0xffffffffu, s, o);
            float nm = fmaxf(m, om);
            s = s * __expf(m - nm) + os * __expf(om - nm);
            m = nm;
        }
        if (kg == 0) {
            g_part[d][rg * 4 + u][blockIdx.x][0] = m;
            g_part[d][rg * 4 + u][blockIdx.x][1] = s;
        }
    }
}

#define K5_SMEM (2 * 64 * 257 * 4)
__global__ void __launch_bounds__(256) pair_gemm_kernel() {
    int d = blockIdx.x;
    const float* A  = g_codes[(d == 0) ? 0 : 1];
    const float* Bm = g_codes[(d == 0) ? 1 : 3];
    extern __shared__ float sh2[];
    float* shA = sh2;
    float* shB = sh2 + 64 * 257;
    int tid = threadIdx.x;
    for (int idx = tid; idx < 64 * 256; idx += 256) {
        int r = idx >> 8, c = idx & 255;
        shA[r * 257 + c] = A[idx];
        shB[r * 257 + c] = Bm[idx];
    }
    __syncthreads();
    int rg = tid >> 4, cg = tid & 15;
    float acc[4][4];
#pragma unroll
    for (int u = 0; u < 4; u++)
#pragma unroll
        for (int v = 0; v < 4; v++) acc[u][v] = 0.f;
#pragma unroll 4
    for (int k = 0; k < 256; k++) {
        float a0 = shA[(rg * 4 + 0) * 257 + k];
        float a1 = shA[(rg * 4 + 1) * 257 + k];
        float a2 = shA[(rg * 4 + 2) * 257 + k];
        float a3 = shA[(rg * 4 + 3) * 257 + k];
        float b0 = shB[(cg * 4 + 0) * 257 + k];
        float b1 = shB[(cg * 4 + 1) * 257 + k];
        float b2 = shB[(cg * 4 + 2) * 257 + k];
        float b3 = shB[(cg * 4 + 3) * 257 + k];
        acc[0][0] += a0 * b0; acc[0][1] += a0 * b1; acc[0][2] += a0 * b2; acc[0][3] += a0 * b3;
        acc[1][0] += a1 * b0; acc[1][1] += a1 * b1; acc[1][2] += a1 * b2; acc[1][3] += a1 * b3;
        acc[2][0] += a2 * b0; acc[2][1] += a2 * b1; acc[2][2] += a2 * b2; acc[2][3] += a2 * b3;
        acc[3][0] += a3 * b0; acc[3][1] += a3 * b1; acc[3][2] += a3 * b2; acc[3][3] += a3 * b3;
    }
#pragma unroll
    for (int u = 0; u < 4; u++)
#pragma unroll
        for (int v = 0; v < 4; v++)
            g_small[d][(rg * 4 + u) * 64 + cg * 4 + v] = G3f * acc[u][v];
}

__device__ float lse_md_row(const float* M, int r, float scale) {
    float mx = -FLT_MAX;
    for (int c2 = 0; c2 < 64; c2++) mx = fmaxf(mx, scale * M[r * 64 + c2]);
    float s = 0.f;
    for (int c2 = 0; c2 < 64; c2++) s += __expf(scale * M[r * 64 + c2] - mx);
    return logf(s) + mx - scale * M[r * 64 + r];
}
__device__ float lse_md_col(const float* M, int c2, float scale) {
    float mx = -FLT_MAX;
    for (int r = 0; r < 64; r++) mx = fmaxf(mx, scale * M[r * 64 + c2]);
    float s = 0.f;
    for (int r = 0; r < 64; r++) s += __expf(scale * M[r * 64 + c2] - mx);
    return logf(s) + mx - scale * M[c2 * 64 + c2];
}

__global__ void finalize_kernel(float* __restrict__ out) {
    __shared__ float sv[8][64];
    int tid = threadIdx.x;
    if (tid < 128) {
        const int d = tid >> 6, i = tid & 63;
        float M = -FLT_MAX, S = 0.f;
        for (int b = 0; b < 256; b++) {
            float m = g_part[d][i][b][0], s = g_part[d][i][b][1];
            float nm = fmaxf(M, m);
            S = S * __expf(M - nm) + s * __expf(m - nm);
            M = nm;
        }
        float pos = 0.f;
        const float* a = g_codes[d];
        const float* b2 = g_codes[(d == 0) ? 3 : 2];
        for (int k = 0; k < NEFc; k++) pos += a[i * NEFc + k] * b2[i * NEFc + k];
        pos *= INV_T;
        float Mf = fmaxf(pos, M);
        float Sf = __expf(pos - Mf) + S * __expf(M - Mf);
        sv[6 + d][i] = logf(Sf) + Mf - pos;
    }
    __syncthreads();
    if (tid < 64) {
        int i = tid;
        sv[0][i] = lse_md_row(g_simT, i, G3f);
        sv[1][i] = lse_md_col(g_simT, i, G3f);
        sv[2][i] = lse_md_row(g_small[0], i, 1.f);
        sv[3][i] = lse_md_col(g_small[0], i, 1.f);
        sv[4][i] = lse_md_row(g_small[1], i, 1.f);
        sv[5][i] = lse_md_col(g_small[1], i, 1.f);
    }
    __syncthreads();
    if (tid == 0) {
        float a[8];
        for (int q2 = 0; q2 < 8; q2++) {
            float s = 0.f;
            for (int k = 0; k < 64; k++) s += sv[q2][k];
            a[q2] = s * (1.f / 64.f);
        }
        out[0] = a[0];
        out[1] = a[1];
        out[2] = a[2];
        out[3] = a[3];
        out[4] = 0.5f * (a[6] + a[7]);
        out[5] = a[4];
        out[6] = a[5];
    }
}

extern "C" void kernel_launch(void* const* d_in, const int* in_sizes, int n_in,
                              void* d_out, int out_size) {
    const float* cnn      = (const float*)d_in[0];
    const float* rnn      = (const float*)d_in[1];
    const float* imgf     = (const float*)d_in[2];
    const float* we       = (const float*)d_in[3];
    const float* cnn_aug  = (const float*)d_in[4];
    const float* rnn_aug  = (const float*)d_in[5];
    const float* queue    = (const float*)d_in[6];
    const float* queue_im = (const float*)d_in[7];
    float* out = (float*)d_out;

    cudaFuncSetAttribute(prep_AX, cudaFuncAttributeMaxDynamicSharedMemorySize, PAX_SMEM);
    cudaFuncSetAttribute(word_mma_kernel, cudaFuncAttributeMaxDynamicSharedMemorySize, WK_SMEM);
    cudaFuncSetAttribute(pair_gemm_kernel, cudaFuncAttributeMaxDynamicSharedMemorySize, K5_SMEM);

    prep_AX<<<dim3(64, 4), 256, PAX_SMEM>>>(imgf);                       // 1
    prep_B<<<2048, 256>>>(we);                                           // 2
    normalize_kernel<<<dim3(64, 4), 256>>>(cnn, rnn, cnn_aug, rnn_aug);  // 3
    word_mma_kernel<<<2048, 256, WK_SMEM>>>();                           // 4  <- ncu capture slot
    moco_gemm_kernel<<<dim3(256, 2), 256>>>(queue, queue_im);            // 5
    pair_gemm_kernel<<<2, 256, K5_SMEM>>>();                             // 6
    finalize_kernel<<<1, 256>>>(out);                                    // 7
}

// round 13
// speedup vs baseline: 1.2398x; 1.0670x over previous
#include <cuda_runtime.h>
#include <cuda_bf16.h>
#include <math.h>
#include <float.h>
#include <stdint.h>

#define Bn   64
#define Tn   32
#define NEFc 256
#define Sn   289
#define SPAD 384
#define S2   320
#define Kq   16384
#define G1f  4.0f
#define G2f  5.0f
#define G3f  10.0f
#define INV_T 20.0f
#define EPSf 1e-8f

// ---------------- device scratch (bf16 single precision copies) ----------------
__device__ uint4 g_A4[64 * SPAD * 256 / 8];   // ctxT [j][s_pad][c] bf16
__device__ uint4 g_X4[64 * 256 * SPAD / 8];   // imgf [j][c][s_pad] bf16
__device__ uint4 g_B4[2048 * 256 / 8];        // we   [i*32+t][c] bf16
__device__ float g_qn[2048];
__device__ float g_codes[4][Bn * NEFc];
__device__ float g_simT[Bn * Bn];
__device__ float g_part[2][Bn][256][2];       // moco per-kblock (max, sumexp)
__device__ float g_small[2][Bn * Bn];

// ---------------- helpers ----------------
__device__ __forceinline__ uint32_t smem_u32(const void* p) {
    uint32_t a;
    asm("{ .reg .u64 t; cvta.to.shared.u64 t, %1; cvt.u32.u64 %0, t; }" : "=r"(a) : "l"(p));
    return a;
}
__device__ __forceinline__ void ldm_x4(uint32_t addr, uint32_t& r0, uint32_t& r1, uint32_t& r2, uint32_t& r3) {
    asm volatile("ldmatrix.sync.aligned.m8n8.x4.shared.b16 {%0,%1,%2,%3}, [%4];"
                 : "=r"(r0), "=r"(r1), "=r"(r2), "=r"(r3) : "r"(addr));
}
#define MMA16816(d, A0, A1, A2, A3, B0, B1)                                   \
    asm volatile("mma.sync.aligned.m16n8k16.row.col.f32.bf16.bf16.f32 "       \
                 "{%0,%1,%2,%3},{%4,%5,%6,%7},{%8,%9},{%0,%1,%2,%3};"          \
                 : "+f"((d)[0]), "+f"((d)[1]), "+f"((d)[2]), "+f"((d)[3])      \
                 : "r"(A0), "r"(A1), "r"(A2), "r"(A3), "r"(B0), "r"(B1))

__device__ __forceinline__ void cp16(uint32_t s, const void* g) {
    asm volatile("cp.async.ca.shared.global [%0], [%1], 16;" :: "r"(s), "l"(g));
}
#define CP_COMMIT() asm volatile("cp.async.commit_group;" ::: "memory")
#define CP_WAIT0()  asm volatile("cp.async.wait_group 0;" ::: "memory")
#define CP_WAIT1()  asm volatile("cp.async.wait_group 1;" ::: "memory")

// ---------------- prep_AX ----------------
#define PAX_SMEM (64 * 385 * 4)
__global__ void __launch_bounds__(256) prep_AX(const float* __restrict__ imgf) {
    const int j = blockIdx.x, ct = blockIdx.y;
    extern __shared__ float tile[];
    const int tid = threadIdx.x;
    const float* base = imgf + ((size_t)j * 256 + ct * 64) * Sn;
    for (int idx = tid; idx < 64 * Sn; idx += 256) {
        int r = idx / Sn, s = idx - r * Sn;
        tile[r * 385 + s] = base[(size_t)r * Sn + s];
    }
    __syncthreads();
    for (int idx = tid; idx < SPAD * 64; idx += 256) {
        const int s = idx >> 6, c = idx & 63;
        float v = (s < Sn) ? tile[c * 385 + s] : 0.f;
        ((__nv_bfloat16*)g_A4)[((size_t)j * SPAD + s) * 256 + ct * 64 + c] = __float2bfloat16(v);
    }
    for (int idx = tid; idx < 64 * S2; idx += 256) {
        const int c = idx / S2, s = idx - c * S2;
        float v = (s < Sn) ? tile[c * 385 + s] : 0.f;
        ((__nv_bfloat16*)g_X4)[((size_t)j * 256 + ct * 64 + c) * SPAD + s] = __float2bfloat16(v);
    }
}

__global__ void prep_B(const float* __restrict__ we) {
    int r = blockIdx.x, c = threadIdx.x;
    float v = we[(size_t)r * 256 + c];
    ((__nv_bfloat16*)g_B4)[(size_t)r * 256 + c] = __float2bfloat16(v);
    __shared__ float red[8];
    float s = v * v;
    for (int o = 16; o; o >>= 1) s += __shfl_down_sync(0xffffffffu, s, o);
    if ((c & 31) == 0) red[c >> 5] = s;
    __syncthreads();
    if (c == 0) {
        float tot = 0.f;
#pragma unroll
        for (int w = 0; w < 8; w++) tot += red[w];
        g_qn[r] = sqrtf(tot);
    }
}

__global__ void normalize_kernel(const float* __restrict__ c0, const float* __restrict__ c1,
                                 const float* __restrict__ c2, const float* __restrict__ c3) {
    int i = blockIdx.x;
    int m = blockIdx.y;
    const float* src = (m == 0) ? c0 : (m == 1) ? c1 : (m == 2) ? c2 : c3;
    int tid = threadIdx.x;
    __shared__ float red[8];
    float v = src[i * NEFc + tid];
    float s = v * v;
    for (int o = 16; o; o >>= 1) s += __shfl_down_sync(0xffffffffu, s, o);
    if ((tid & 31) == 0) red[tid >> 5] = s;
    __syncthreads();
    float tot = 0.f;
#pragma unroll
    for (int w = 0; w < 8; w++) tot += red[w];
    g_codes[m][i * NEFc + tid] = v / fmaxf(sqrtf(tot), EPSf);
}

// ---------------- word kernel smem layout (bytes) ----------------
#define OFF_SC   0          // scores 320x65 f32 = 83200
#define OFF_W    83200      // W 64x528 = 33792
#define OFF_AB   116992     // A buf 128x528 = 67584 -> end 184576
#define OFF_E    116992     // e 64x784 = 50176 (after phase1)
#define OFF_XB0  0          // X buf0 128x272 = 34816 (after epilogue)
#define OFF_XB1  34816
#define OFF_DEN  184576
#define OFF_NUM  184832
#define OFF_WN2  185088
#define OFF_RMAX 185344     // 2560
#define OFF_RINV 187904     // 2560
#define WK_SMEM  190464

__global__ void __launch_bounds__(256, 1) word_mma_kernel() {
    const int j  = blockIdx.x >> 5;
    const int ip = blockIdx.x & 31;
    extern __shared__ char sm[];
    const uint32_t sb = smem_u32(sm);
    const int tid = threadIdx.x, lane = tid & 31, w = tid >> 5;

    float* scp   = (float*)(sm + OFF_SC);
    float* denA  = (float*)(sm + OFF_DEN);
    float* numA  = (float*)(sm + OFF_NUM);
    float* wn2A  = (float*)(sm + OFF_WN2);
    float* rmaxp = (float*)(sm + OFF_RMAX);
    float* rinvp = (float*)(sm + OFF_RINV);
    if (tid < 192) denA[tid] = 0.f;

    // prologue: W (64x528) and A rows 0..127
    for (int idx = tid; idx < 2048; idx += 256) {
        int r = idx >> 5, cb = idx & 31;
        cp16(sb + OFF_W + r * 528 + cb * 16, g_B4 + (((size_t)(ip * 64 + r)) << 5) + cb);
    }
    for (int idx = tid; idx < 4096; idx += 256) {
        int r = idx >> 5, cb = idx & 31;
        cp16(sb + OFF_AB + r * 528 + cb * 16, g_A4 + (((size_t)j * SPAD + r) << 5) + cb);
    }
    CP_COMMIT();

    const uint32_t rowA  = (lane & 7) + ((lane >> 3) & 1) * 8;
    const uint32_t coffA = (lane >> 4) * 16;
    const uint32_t boffB = ((lane >> 3) & 1) * 16;

    // ===== phase 1a: 2 chunks of 128 s-rows; warps 4m x 2n; FULL K per warp =====
    {
        const int wm = w >> 1;        // 0..3: m group of 32 within 128-row chunk
        const int wn = w & 1;         // n group of 32
        const uint32_t bRow = 32u * wn + (((uint32_t)lane >> 4) << 3) + (lane & 7);
        const uint32_t bB = sb + OFF_W + bRow * 528 + boffB;

        for (int ch = 0; ch < 2; ch++) {
            CP_WAIT0();
            __syncthreads();

            float acc[2][4][4];
#pragma unroll
            for (int mi = 0; mi < 2; mi++)
#pragma unroll
                for (int nf = 0; nf < 4; nf++)
#pragma unroll
                    for (int r = 0; r < 4; r++) acc[mi][nf][r] = 0.f;

            const uint32_t aB = sb + OFF_AB + (wm * 32 + rowA) * 528 + coffA;

#pragma unroll 4
            for (int k = 0; k < 16; k++) {
                const uint32_t kb = (uint32_t)k * 32u;
                uint32_t a0, a1, a2, a3, a4, a5, a6, a7;
                uint32_t h0, h1, h2, h3, h4, h5, h6, h7;
                ldm_x4(aB + kb, a0, a1, a2, a3);
                ldm_x4(aB + 16 * 528 + kb, a4, a5, a6, a7);
                ldm_x4(bB + kb, h0, h1, h2, h3);
                ldm_x4(bB + 16 * 528 + kb, h4, h5, h6, h7);
                MMA16816(acc[0][0], a0, a1, a2, a3, h0, h1);
                MMA16816(acc[0][1], a0, a1, a2, a3, h2, h3);
                MMA16816(acc[0][2], a0, a1, a2, a3, h4, h5);
                MMA16816(acc[0][3], a0, a1, a2, a3, h6, h7);
                MMA16816(acc[1][0], a4, a5, a6, a7, h0, h1);
                MMA16816(acc[1][1], a4, a5, a6, a7, h2, h3);
                MMA16816(acc[1][2], a4, a5, a6, a7, h4, h5);
                MMA16816(acc[1][3], a4, a5, a6, a7, h6, h7);
            }
            __syncthreads();   // A buffer fully consumed

            // issue next load (chunk1: rows 128..255; after chunk1: tail rows 256..319)
            if (ch == 0) {
                for (int idx = tid; idx < 4096; idx += 256) {
                    int r = idx >> 5, cb = idx & 31;
                    cp16(sb + OFF_AB + r * 528 + cb * 16,
                         g_A4 + (((size_t)j * SPAD + 128 + r) << 5) + cb);
                }
                CP_COMMIT();
            } else {
                for (int idx = tid; idx < 2048; idx += 256) {
                    int r = idx >> 5, cb = idx & 31;
                    cp16(sb + OFF_AB + r * 528 + cb * 16,
                         g_A4 + (((size_t)j * SPAD + 256 + r) << 5) + cb);
                }
                CP_COMMIT();
            }

            // direct store (no k-merge)
#pragma unroll
            for (int mi = 0; mi < 2; mi++) {
                const int row = ch * 128 + wm * 32 + mi * 16 + (lane >> 2);
#pragma unroll
                for (int nf = 0; nf < 4; nf++) {
                    const int col = wn * 32 + nf * 8 + (lane & 3) * 2;
                    scp[row * 65 + col]           = acc[mi][nf][0];
                    scp[row * 65 + col + 1]       = acc[mi][nf][1];
                    scp[(row + 8) * 65 + col]     = acc[mi][nf][2];
                    scp[(row + 8) * 65 + col + 1] = acc[mi][nf][3];
                }
            }
        }
    }

    // ===== phase 1b: tail chunk (rows 256..319); warps 2m x 2n x 2k; store+merge =====
    {
        const int wk  = w >> 2;
        const int wm1 = (w >> 1) & 1;
        const int wn1 = w & 1;
        const uint32_t bRow1 = 32u * wn1 + (((uint32_t)lane >> 4) << 3) + (lane & 7);

        CP_WAIT0();
        __syncthreads();

        float acc[2][4][4];
#pragma unroll
        for (int mi = 0; mi < 2; mi++)
#pragma unroll
            for (int nf = 0; nf < 4; nf++)
#pragma unroll
                for (int r = 0; r < 4; r++) acc[mi][nf][r] = 0.f;

        const uint32_t aB = sb + OFF_AB + (wm1 * 32 + rowA) * 528 + coffA + (uint32_t)wk * 256u;
        const uint32_t bB = sb + OFF_W + bRow1 * 528 + boffB + (uint32_t)wk * 256u;

#pragma unroll
        for (int k = 0; k < 8; k++) {
            const uint32_t kb = (uint32_t)k * 32u;
            uint32_t a0, a1, a2, a3, a4, a5, a6, a7;
            uint32_t h0, h1, h2, h3, h4, h5, h6, h7;
            ldm_x4(aB + kb, a0, a1, a2, a3);
            ldm_x4(aB + 16 * 528 + kb, a4, a5, a6, a7);
            ldm_x4(bB + kb, h0, h1, h2, h3);
            ldm_x4(bB + 16 * 528 + kb, h4, h5, h6, h7);
            MMA16816(acc[0][0], a0, a1, a2, a3, h0, h1);
            MMA16816(acc[0][1], a0, a1, a2, a3, h2, h3);
            MMA16816(acc[0][2], a0, a1, a2, a3, h4, h5);
            MMA16816(acc[0][3], a0, a1, a2, a3, h6, h7);
            MMA16816(acc[1][0], a4, a5, a6, a7, h0, h1);
            MMA16816(acc[1][1], a4, a5, a6, a7, h2, h3);
            MMA16816(acc[1][2], a4, a5, a6, a7, h4, h5);
            MMA16816(acc[1][3], a4, a5, a6, a7, h6, h7);
        }

        if (wk == 0) {
#pragma unroll
            for (int mi = 0; mi < 2; mi++) {
                const int row = 256 + wm1 * 32 + mi * 16 + (lane >> 2);
#pragma unroll
                for (int nf = 0; nf < 4; nf++) {
                    const int col = wn1 * 32 + nf * 8 + (lane & 3) * 2;
                    scp[row * 65 + col]           = acc[mi][nf][0];
                    scp[row * 65 + col + 1]       = acc[mi][nf][1];
                    scp[(row + 8) * 65 + col]     = acc[mi][nf][2];
                    scp[(row + 8) * 65 + col + 1] = acc[mi][nf][3];
                }
            }
        }
        __syncthreads();
        if (wk == 1) {
#pragma unroll
            for (int mi = 0; mi < 2; mi++) {
                const int row = 256 + wm1 * 32 + mi * 16 + (lane >> 2);
#pragma unroll
                for (int nf = 0; nf < 4; nf++) {
                    const int col = wn1 * 32 + nf * 8 + (lane & 3) * 2;
                    scp[row * 65 + col]           += acc[mi][nf][0];
                    scp[row * 65 + col + 1]       += acc[mi][nf][1];
                    scp[(row + 8) * 65 + col]     += acc[mi][nf][2];
                    scp[(row + 8) * 65 + col + 1] += acc[mi][nf][3];
                }
            }
        }
    }
    __syncthreads();

    // ===== epilogue: softmaxes, den/num, e -> smem bf16 (s < 320) =====
    for (int r = tid; r < 320; r += 256) {
#pragma unroll
        for (int h = 0; h < 2; h++) {
            float m = -FLT_MAX;
            for (int t = 0; t < 32; t++) m = fmaxf(m, scp[r * 65 + h * 32 + t]);
            float s = 0.f;
            for (int t = 0; t < 32; t++) s += __expf(scp[r * 65 + h * 32 + t] - m);
            rmaxp[r * 2 + h] = m;
            rinvp[r * 2 + h] = 1.f / s;
        }
    }
    __syncthreads();
    {
        const int t = tid & 63, sg = tid >> 6, h = t >> 5;
        float dpart = 0.f, npart = 0.f;
        __nv_bfloat16* eP = (__nv_bfloat16*)(sm + OFF_E);
        for (int k2 = 0; k2 < 80; k2++) {
            const int s = sg * 80 + k2;
            float e = 0.f;
            if (s < Sn) {
                float sv = scp[s * 65 + t];
                float a1 = __expf(sv - rmaxp[s * 2 + h]) * rinvp[s * 2 + h];
                e = __expf(G1f * a1);
                dpart += e;
                npart += e * sv;
            }
            eP[t * 392 + s] = __float2bfloat16(e);
        }
        atomicAdd(&denA[t], dpart);
        atomicAdd(&numA[t], npart);
    }
    __syncthreads();   // scp consumed; X buffers may overwrite it

    // ===== phase 2: wC = X @ e^T; K = 320; chunks {128,128,64} x 2 m-tiles =====
    {
        const int wm2 = w >> 1;
        const int wn2 = w & 1;
        const uint32_t bRow2 = 32u * wn2 + (((uint32_t)lane >> 4) << 3) + (lane & 7);

        for (int idx = tid; idx < 2048; idx += 256) {
            int r = idx >> 4, cb = idx & 15;
            cp16(sb + OFF_XB0 + r * 272 + cb * 16, g_X4 + (((size_t)(j * 256 + r)) * 48) + cb);
        }
        CP_COMMIT();

        float acc2[2][4][4];
        for (int q = 0; q < 6; q++) {
            const int sc3 = q % 3;
            const uint32_t xb = sb + (q & 1 ? OFF_XB1 : OFF_XB0);
            if (q + 1 < 6) {
                const int mtn = (q + 1) / 3, sc3n = (q + 1) % 3;
                uint32_t dst = sb + ((q + 1) & 1 ? OFF_XB1 : OFF_XB0);
                if (sc3n < 2) {
                    for (int idx = tid; idx < 2048; idx += 256) {
                        int r = idx >> 4, cb = idx & 15;
                        cp16(dst + r * 272 + cb * 16,
                             g_X4 + (((size_t)(j * 256 + mtn * 128 + r)) * 48) + sc3n * 16 + cb);
                    }
                } else {
                    for (int idx = tid; idx < 1024; idx += 256) {
                        int r = idx >> 3, cb = idx & 7;
                        cp16(dst + r * 272 + cb * 16,
                             g_X4 + (((size_t)(j * 256 + mtn * 128 + r)) * 48) + 32 + cb);
                    }
                }
                CP_COMMIT();
                CP_WAIT1();
            } else {
                CP_WAIT0();
            }
            __syncthreads();

            if (sc3 == 0) {
#pragma unroll
                for (int mi = 0; mi < 2; mi++)
#pragma unroll
                    for (int n = 0; n < 4; n++)
#pragma unroll
                        for (int r = 0; r < 4; r++) acc2[mi][n][r] = 0.f;
            }

            const uint32_t eB0 = sb + OFF_E + bRow2 * 784 + (uint32_t)sc3 * 256u + boffB;
            const uint32_t eB1 = eB0 + 16 * 784;
            const uint32_t xA  = xb + (wm2 * 32 + rowA) * 272 + coffA;

            const int kmax = (sc3 == 2) ? 4 : 8;
#pragma unroll 4
            for (int k = 0; k < kmax; k++) {
                const uint32_t kb = (uint32_t)k * 32u;
                uint32_t x0, x1, x2, x3, x4, x5, x6, x7;
                uint32_t e0, e1, e2, e3, e4, e5, e6, e7;
                ldm_x4(xA + kb, x0, x1, x2, x3);
                ldm_x4(xA + 16 * 272 + kb, x4, x5, x6, x7);
                ldm_x4(eB0 + kb, e0, e1, e2, e3);
                ldm_x4(eB1 + kb, e4, e5, e6, e7);
                MMA16816(acc2[0][0], x0, x1, x2, x3, e0, e1);
                MMA16816(acc2[0][1], x0, x1, x2, x3, e2, e3);
                MMA16816(acc2[0][2], x0, x1, x2, x3, e4, e5);
                MMA16816(acc2[0][3], x0, x1, x2, x3, e6, e7);
                MMA16816(acc2[1][0], x4, x5, x6, x7, e0, e1);
                MMA16816(acc2[1][1], x4, x5, x6, x7, e2, e3);
                MMA16816(acc2[1][2], x4, x5, x6, x7, e4, e5);
                MMA16816(acc2[1][3], x4, x5, x6, x7, e6, e7);
            }
            __syncthreads();   // xb fully consumed

            if (sc3 == 2) {
#pragma unroll
                for (int n = 0; n < 4; n++) {
                    float v0 = 0.f, v1 = 0.f;
#pragma unroll
                    for (int mi = 0; mi < 2; mi++) {
                        v0 += acc2[mi][n][0] * acc2[mi][n][0] + acc2[mi][n][2] * acc2[mi][n][2];
                        v1 += acc2[mi][n][1] * acc2[mi][n][1] + acc2[mi][n][3] * acc2[mi][n][3];
                    }
#pragma unroll
                    for (int o = 4; o <= 16; o <<= 1) {
                        v0 += __shfl_xor_sync(0xffffffffu, v0, o);
                        v1 += __shfl_xor_sync(0xffffffffu, v1, o);
                    }
                    if (lane < 4) {
                        const int t = (4 * wn2 + n) * 8 + lane * 2;
                        atomicAdd(&wn2A[t], v0);
                        atomicAdd(&wn2A[t + 1], v1);
                    }
                }
            }
        }
    }
    __syncthreads();

    if (tid < 64) {
        const int t = tid;
        float dinv = 1.f / denA[t];
        float wnv = sqrtf(wn2A[t]) * dinv;
        float nm = numA[t] * dinv;
        float qnv = g_qn[ip * 64 + t];
        float cosv = nm / fmaxf(qnv * wnv, EPSf);
        float v = G2f * cosv;
        float m = v;
        for (int o = 16; o; o >>= 1) m = fmaxf(m, __shfl_xor_sync(0xffffffffu, m, o));
        float e = __expf(v - m);
        for (int o = 16; o; o >>= 1) e += __shfl_xor_sync(0xffffffffu, e, o);
        if (lane == 0) g_simT[j * 64 + ip * 2 + (tid >> 5)] = logf(e) + m;
    }
}

// ---------------- moco GEMM with fused per-block LSE ----------------
__global__ void __launch_bounds__(256) moco_gemm_kernel(const float* __restrict__ queue,
                                                        const float* __restrict__ queue_im) {
    int k0 = blockIdx.x * 64;
    int d = blockIdx.y;
    const float* A = g_codes[d];
    const float* Q = (d == 0) ? queue : queue_im;
    __shared__ float sA[64 * 33];
    __shared__ float sB[32 * 65];
    int tid = threadIdx.x;
    int rg = tid >> 4;
    int kg = tid & 15;
    float acc[4][4];
#pragma unroll
    for (int u = 0; u < 4; u++)
#pragma unroll
        for (int v = 0; v < 4; v++) acc[u][v] = 0.f;
    for (int c0 = 0; c0 < NEFc; c0 += 32) {
        __syncthreads();
        for (int idx = tid; idx < 64 * 32; idx += 256) {
            int r = idx >> 5, cc = idx & 31;
            sA[r * 33 + cc] = A[r * NEFc + c0 + cc];
        }
        for (int idx = tid; idx < 32 * 64; idx += 256) {
            int cc = idx >> 6, kk = idx & 63;
            sB[cc * 65 + kk] = Q[(size_t)(c0 + cc) * Kq + k0 + kk];
        }
        __syncthreads();
#pragma unroll 4
        for (int cc = 0; cc < 32; cc++) {
            float a0 = sA[(rg * 4 + 0) * 33 + cc];
            float a1 = sA[(rg * 4 + 1) * 33 + cc];
            float a2 = sA[(rg * 4 + 2) * 33 + cc];
            float a3 = sA[(rg * 4 + 3) * 33 + cc];
#pragma unroll
            for (int v = 0; v < 4; v++) {
                float b = sB[cc * 65 + kg + 16 * v];
                acc[0][v] += a0 * b;
                acc[1][v] += a1 * b;
                acc[2][v] += a2 * b;
                acc[3][v] += a3 * b;
            }
        }
    }
#pragma unroll
    for (int u = 0; u < 4; u++) {
        float z0 = acc[u][0] * INV_T, z1 = acc[u][1] * INV_T;
        float z2 = acc[u][2] * INV_T, z3 = acc[u][3] * INV_T;
        float m = fmaxf(fmaxf(z0, z1), fmaxf(z2, z3));
        float s = __expf(z0 - m) + __expf(z1 - m) + __expf(z2 - m) + __expf(z3 - m);
#pragma unroll
        for (int o = 1; o < 16; o <<= 1) {
            float om = __shfl_xor_sync(0xffffffffu, m, o);
            float os = __shfl_xor_sync(0xffffffffu, s, o);
            float nm = fmaxf(m, om);
            s = s * __expf(m - nm) + os * __expf(om - nm);
            m = nm;
        }
        if (kg == 0) {
            g_part[d][rg * 4 + u][blockIdx.x][0] = m;
            g_part[d][rg * 4 + u][blockIdx.x][1] = s;
        }
    }
}

// ---------------- pair GEMMs: grid (16, 2), 4x64 tile per block ----------------
#define K5_SMEM ((64 * 257 + 4 * 256) * 4)
__global__ void __launch_bounds__(256) pair_gemm_kernel() {
    const int rb = blockIdx.x, d = blockIdx.y;
    const float* A  = g_codes[(d == 0) ? 0 : 1];
    const float* Bm = g_codes[(d == 0) ? 1 : 3];
    extern __shared__ float sh2[];
    float* shB = sh2;              // [64][257]
    float* shA = sh2 + 64 * 257;   // [4][256]
    const int tid = threadIdx.x;
    for (int idx = tid; idx < 64 * 256; idx += 256) {
        int r = idx >> 8, c = idx & 255;
        shB[r * 257 + c] = Bm[idx];
    }
    for (int idx = tid; idx < 4 * 256; idx += 256)
        shA[idx] = A[rb * 4 * 256 + idx];
    __syncthreads();
    const int u = tid >> 6, v = tid & 63;
    float s = 0.f;
#pragma unroll 8
    for (int k = 0; k < 256; k++)
        s += shA[u * 256 + k] * shB[v * 257 + k];
    g_small[d][(rb * 4 + u) * 64 + v] = G3f * s;
}

__device__ float lse_md_row(const float* M, int r, float scale) {
    float mx = -FLT_MAX;
    for (int c2 = 0; c2 < 64; c2++) mx = fmaxf(mx, scale * M[r * 64 + c2]);
    float s = 0.f;
    for (int c2 = 0; c2 < 64; c2++) s += __expf(scale * M[r * 64 + c2] - mx);
    return logf(s) + mx - scale * M[r * 64 + r];
}
__device__ float lse_md_col(const float* M, int c2, float scale) {
    float mx = -FLT_MAX;
    for (int r = 0; r < 64; r++) mx = fmaxf(mx, scale * M[r * 64 + c2]);
    float s = 0.f;
    for (int r = 0; r < 64; r++) s += __expf(scale * M[r * 64 + c2] - mx);
    return logf(s) + mx - scale * M[c2 * 64 + c2];
}

__global__ void finalize_kernel(float* __restrict__ out) {
    __shared__ float sv[8][64];
    int tid = threadIdx.x;
    if (tid < 128) {
        const int d = tid >> 6, i = tid & 63;
        float M = -FLT_MAX, S = 0.f;
        for (int b = 0; b < 256; b++) {
            float m = g_part[d][i][b][0], s = g_part[d][i][b][1];
            float nm = fmaxf(M, m);
            S = S * __expf(M - nm) + s * __expf(m - nm);
            M = nm;
        }
        float pos = 0.f;
        const float* a = g_codes[d];
        const float* b2 = g_codes[(d == 0) ? 3 : 2];
        for (int k = 0; k < NEFc; k++) pos += a[i * NEFc + k] * b2[i * NEFc + k];
        pos *= INV_T;
        float Mf = fmaxf(pos, M);
        float Sf = __expf(pos - Mf) + S * __expf(M - Mf);
        sv[6 + d][i] = logf(Sf) + Mf - pos;
    }
    __syncthreads();
    if (tid < 64) {
        int i = tid;
        sv[0][i] = lse_md_row(g_simT, i, G3f);
        sv[1][i] = lse_md_col(g_simT, i, G3f);
        sv[2][i] = lse_md_row(g_small[0], i, 1.f);
        sv[3][i] = lse_md_col(g_small[0], i, 1.f);
        sv[4][i] = lse_md_row(g_small[1], i, 1.f);
        sv[5][i] = lse_md_col(g_small[1], i, 1.f);
    }
    __syncthreads();
    if (tid == 0) {
        float a[8];
        for (int q2 = 0; q2 < 8; q2++) {
            float s = 0.f;
            for (int k = 0; k < 64; k++) s += sv[q2][k];
            a[q2] = s * (1.f / 64.f);
        }
        out[0] = a[0];
        out[1] = a[1];
        out[2] = a[2];
        out[3] = a[3];
        out[4] = 0.5f * (a[6] + a[7]);
        out[5] = a[4];
        out[6] = a[5];
    }
}

extern "C" void kernel_launch(void* const* d_in, const int* in_sizes, int n_in,
                              void* d_out, int out_size) {
    const float* cnn      = (const float*)d_in[0];
    const float* rnn      = (const float*)d_in[1];
    const float* imgf     = (const float*)d_in[2];
    const float* we       = (const float*)d_in[3];
    const float* cnn_aug  = (const float*)d_in[4];
    const float* rnn_aug  = (const float*)d_in[5];
    const float* queue    = (const float*)d_in[6];
    const float* queue_im = (const float*)d_in[7];
    float* out = (float*)d_out;

    cudaFuncSetAttribute(prep_AX, cudaFuncAttributeMaxDynamicSharedMemorySize, PAX_SMEM);
    cudaFuncSetAttribute(word_mma_kernel, cudaFuncAttributeMaxDynamicSharedMemorySize, WK_SMEM);
    cudaFuncSetAttribute(pair_gemm_kernel, cudaFuncAttributeMaxDynamicSharedMemorySize, K5_SMEM);

    prep_AX<<<dim3(64, 4), 256, PAX_SMEM>>>(imgf);                       // 1
    prep_B<<<2048, 256>>>(we);                                           // 2
    normalize_kernel<<<dim3(64, 4), 256>>>(cnn, rnn, cnn_aug, rnn_aug);  // 3
    word_mma_kernel<<<2048, 256, WK_SMEM>>>();                           // 4  <- ncu capture slot
    moco_gemm_kernel<<<dim3(256, 2), 256>>>(queue, queue_im);            // 5
    pair_gemm_kernel<<<dim3(16, 2), 256, K5_SMEM>>>();                   // 6
    finalize_kernel<<<1, 256>>>(out);                                    // 7
}

// round 14
// speedup vs baseline: 1.2451x; 1.0042x over previous
#include <cuda_runtime.h>
#include <cuda_bf16.h>
#include <math.h>
#include <float.h>
#include <stdint.h>

#define Bn   64
#define Tn   32
#define NEFc 256
#define Sn   289
#define SPAD 384
#define S2   304
#define Kq   16384
#define G1f  4.0f
#define G2f  5.0f
#define G3f  10.0f
#define INV_T 20.0f
#define EPSf 1e-8f

// ---------------- device scratch (bf16 single precision copies) ----------------
__device__ uint4 g_A4[64 * SPAD * 256 / 8];   // ctxT [j][s_pad][c] bf16
__device__ uint4 g_X4[64 * 256 * SPAD / 8];   // imgf [j][c][s_pad] bf16
__device__ uint4 g_B4[2048 * 256 / 8];        // we   [i*32+t][c] bf16
__device__ float g_qn[2048];
__device__ float g_codes[4][Bn * NEFc];
__device__ float g_simT[Bn * Bn];
__device__ float g_part[2][Bn][256][2];       // moco per-kblock (max, sumexp)
__device__ float g_small[2][Bn * Bn];

// ---------------- helpers ----------------
__device__ __forceinline__ uint32_t smem_u32(const void* p) {
    uint32_t a;
    asm("{ .reg .u64 t; cvta.to.shared.u64 t, %1; cvt.u32.u64 %0, t; }" : "=r"(a) : "l"(p));
    return a;
}
__device__ __forceinline__ void ldm_x4(uint32_t addr, uint32_t& r0, uint32_t& r1, uint32_t& r2, uint32_t& r3) {
    asm volatile("ldmatrix.sync.aligned.m8n8.x4.shared.b16 {%0,%1,%2,%3}, [%4];"
                 : "=r"(r0), "=r"(r1), "=r"(r2), "=r"(r3) : "r"(addr));
}
#define MMA16816(d, A0, A1, A2, A3, B0, B1)                                   \
    asm volatile("mma.sync.aligned.m16n8k16.row.col.f32.bf16.bf16.f32 "       \
                 "{%0,%1,%2,%3},{%4,%5,%6,%7},{%8,%9},{%0,%1,%2,%3};"          \
                 : "+f"((d)[0]), "+f"((d)[1]), "+f"((d)[2]), "+f"((d)[3])      \
                 : "r"(A0), "r"(A1), "r"(A2), "r"(A3), "r"(B0), "r"(B1))

__device__ __forceinline__ void cp16(uint32_t s, const void* g) {
    asm volatile("cp.async.ca.shared.global [%0], [%1], 16;" :: "r"(s), "l"(g));
}
#define CP_COMMIT() asm volatile("cp.async.commit_group;" ::: "memory")
#define CP_WAIT0()  asm volatile("cp.async.wait_group 0;" ::: "memory")
#define CP_WAIT1()  asm volatile("cp.async.wait_group 1;" ::: "memory")

// ---------------- prep_AX ----------------
#define PAX_SMEM (64 * 385 * 4)
__global__ void __launch_bounds__(256) prep_AX(const float* __restrict__ imgf) {
    const int j = blockIdx.x, ct = blockIdx.y;
    extern __shared__ float tile[];
    const int tid = threadIdx.x;
    const float* base = imgf + ((size_t)j * 256 + ct * 64) * Sn;
    for (int idx = tid; idx < 64 * Sn; idx += 256) {
        int r = idx / Sn, s = idx - r * Sn;
        tile[r * 385 + s] = base[(size_t)r * Sn + s];
    }
    __syncthreads();
    for (int idx = tid; idx < SPAD * 64; idx += 256) {
        const int s = idx >> 6, c = idx & 63;
        float v = (s < Sn) ? tile[c * 385 + s] : 0.f;
        ((__nv_bfloat16*)g_A4)[((size_t)j * SPAD + s) * 256 + ct * 64 + c] = __float2bfloat16(v);
    }
    for (int idx = tid; idx < 64 * S2; idx += 256) {
        const int c = idx / S2, s = idx - c * S2;
        float v = (s < Sn) ? tile[c * 385 + s] : 0.f;
        ((__nv_bfloat16*)g_X4)[((size_t)j * 256 + ct * 64 + c) * SPAD + s] = __float2bfloat16(v);
    }
}

__global__ void prep_B(const float* __restrict__ we) {
    int r = blockIdx.x, c = threadIdx.x;
    float v = we[(size_t)r * 256 + c];
    ((__nv_bfloat16*)g_B4)[(size_t)r * 256 + c] = __float2bfloat16(v);
    __shared__ float red[8];
    float s = v * v;
    for (int o = 16; o; o >>= 1) s += __shfl_down_sync(0xffffffffu, s, o);
    if ((c & 31) == 0) red[c >> 5] = s;
    __syncthreads();
    if (c == 0) {
        float tot = 0.f;
#pragma unroll
        for (int w = 0; w < 8; w++) tot += red[w];
        g_qn[r] = sqrtf(tot);
    }
}

__global__ void normalize_kernel(const float* __restrict__ c0, const float* __restrict__ c1,
                                 const float* __restrict__ c2, const float* __restrict__ c3) {
    int i = blockIdx.x;
    int m = blockIdx.y;
    const float* src = (m == 0) ? c0 : (m == 1) ? c1 : (m == 2) ? c2 : c3;
    int tid = threadIdx.x;
    __shared__ float red[8];
    float v = src[i * NEFc + tid];
    float s = v * v;
    for (int o = 16; o; o >>= 1) s += __shfl_down_sync(0xffffffffu, s, o);
    if ((tid & 31) == 0) red[tid >> 5] = s;
    __syncthreads();
    float tot = 0.f;
#pragma unroll
    for (int w = 0; w < 8; w++) tot += red[w];
    g_codes[m][i * NEFc + tid] = v / fmaxf(sqrtf(tot), EPSf);
}

// ---------------- word kernel smem layout (bytes) ----------------
#define OFF_SC   0          // scores 320x65 f32 = 83200
#define OFF_W    83200      // W 64x528 = 33792
#define OFF_AB   116992     // A buf 128x528 = 67584 -> end 184576
#define OFF_XW   83200      // X chunk-0 (W region after phase 1), 34816 fits 83200..118016
#define OFF_E    118016     // e 64x784 = 50176 -> 168192
#define OFF_XB0  0          // X bufs after epilogue
#define OFF_XB1  34816
#define OFF_DEN  184576
#define OFF_NUM  184832
#define OFF_WN2  185088
#define OFF_RMAX 185344     // 2560
#define OFF_RINV 187904     // 2560
#define WK_SMEM  190464

__global__ void __launch_bounds__(256, 1) word_mma_kernel() {
    const int j  = blockIdx.x >> 5;
    const int ip = blockIdx.x & 31;
    extern __shared__ char sm[];
    const uint32_t sb = smem_u32(sm);
    const int tid = threadIdx.x, lane = tid & 31, w = tid >> 5;

    float* scp   = (float*)(sm + OFF_SC);
    float* denA  = (float*)(sm + OFF_DEN);
    float* numA  = (float*)(sm + OFF_NUM);
    float* wn2A  = (float*)(sm + OFF_WN2);
    float* rmaxp = (float*)(sm + OFF_RMAX);
    float* rinvp = (float*)(sm + OFF_RINV);
    if (tid < 192) denA[tid] = 0.f;

    // prologue: W (64x528) and A rows 0..127
    for (int idx = tid; idx < 2048; idx += 256) {
        int r = idx >> 5, cb = idx & 31;
        cp16(sb + OFF_W + r * 528 + cb * 16, g_B4 + (((size_t)(ip * 64 + r)) << 5) + cb);
    }
    for (int idx = tid; idx < 4096; idx += 256) {
        int r = idx >> 5, cb = idx & 31;
        cp16(sb + OFF_AB + r * 528 + cb * 16, g_A4 + (((size_t)j * SPAD + r) << 5) + cb);
    }
    CP_COMMIT();

    const uint32_t rowA  = (lane & 7) + ((lane >> 3) & 1) * 8;
    const uint32_t coffA = (lane >> 4) * 16;
    const uint32_t boffB = ((lane >> 3) & 1) * 16;

    // ===== phase 1a: 2 chunks of 128 s-rows; warps 4m x 2n; FULL K per warp =====
    {
        const int wm = w >> 1;
        const int wn = w & 1;
        const uint32_t bRow = 32u * wn + (((uint32_t)lane >> 4) << 3) + (lane & 7);
        const uint32_t bB = sb + OFF_W + bRow * 528 + boffB;

        for (int ch = 0; ch < 2; ch++) {
            CP_WAIT0();
            __syncthreads();

            float acc[2][4][4];
#pragma unroll
            for (int mi = 0; mi < 2; mi++)
#pragma unroll
                for (int nf = 0; nf < 4; nf++)
#pragma unroll
                    for (int r = 0; r < 4; r++) acc[mi][nf][r] = 0.f;

            const uint32_t aB = sb + OFF_AB + (wm * 32 + rowA) * 528 + coffA;

#pragma unroll 4
            for (int k = 0; k < 16; k++) {
                const uint32_t kb = (uint32_t)k * 32u;
                uint32_t a0, a1, a2, a3, a4, a5, a6, a7;
                uint32_t h0, h1, h2, h3, h4, h5, h6, h7;
                ldm_x4(aB + kb, a0, a1, a2, a3);
                ldm_x4(aB + 16 * 528 + kb, a4, a5, a6, a7);
                ldm_x4(bB + kb, h0, h1, h2, h3);
                ldm_x4(bB + 16 * 528 + kb, h4, h5, h6, h7);
                MMA16816(acc[0][0], a0, a1, a2, a3, h0, h1);
                MMA16816(acc[0][1], a0, a1, a2, a3, h2, h3);
                MMA16816(acc[0][2], a0, a1, a2, a3, h4, h5);
                MMA16816(acc[0][3], a0, a1, a2, a3, h6, h7);
                MMA16816(acc[1][0], a4, a5, a6, a7, h0, h1);
                MMA16816(acc[1][1], a4, a5, a6, a7, h2, h3);
                MMA16816(acc[1][2], a4, a5, a6, a7, h4, h5);
                MMA16816(acc[1][3], a4, a5, a6, a7, h6, h7);
            }
            __syncthreads();   // A buffer fully consumed

            if (ch == 0) {
                for (int idx = tid; idx < 4096; idx += 256) {
                    int r = idx >> 5, cb = idx & 31;
                    cp16(sb + OFF_AB + r * 528 + cb * 16,
                         g_A4 + (((size_t)j * SPAD + 128 + r) << 5) + cb);
                }
                CP_COMMIT();
            } else {
                for (int idx = tid; idx < 2048; idx += 256) {
                    int r = idx >> 5, cb = idx & 31;
                    cp16(sb + OFF_AB + r * 528 + cb * 16,
                         g_A4 + (((size_t)j * SPAD + 256 + r) << 5) + cb);
                }
                CP_COMMIT();
            }

#pragma unroll
            for (int mi = 0; mi < 2; mi++) {
                const int row = ch * 128 + wm * 32 + mi * 16 + (lane >> 2);
#pragma unroll
                for (int nf = 0; nf < 4; nf++) {
                    const int col = wn * 32 + nf * 8 + (lane & 3) * 2;
                    scp[row * 65 + col]           = acc[mi][nf][0];
                    scp[row * 65 + col + 1]       = acc[mi][nf][1];
                    scp[(row + 8) * 65 + col]     = acc[mi][nf][2];
                    scp[(row + 8) * 65 + col + 1] = acc[mi][nf][3];
                }
            }
        }
    }

    // ===== phase 1b: tail chunk (rows 256..319); warps 2m x 2n x 2k; store+merge =====
    {
        const int wk  = w >> 2;
        const int wm1 = (w >> 1) & 1;
        const int wn1 = w & 1;
        const uint32_t bRow1 = 32u * wn1 + (((uint32_t)lane >> 4) << 3) + (lane & 7);

        CP_WAIT0();
        __syncthreads();

        float acc[2][4][4];
#pragma unroll
        for (int mi = 0; mi < 2; mi++)
#pragma unroll
            for (int nf = 0; nf < 4; nf++)
#pragma unroll
                for (int r = 0; r < 4; r++) acc[mi][nf][r] = 0.f;

        const uint32_t aB = sb + OFF_AB + (wm1 * 32 + rowA) * 528 + coffA + (uint32_t)wk * 256u;
        const uint32_t bB = sb + OFF_W + bRow1 * 528 + boffB + (uint32_t)wk * 256u;

#pragma unroll
        for (int k = 0; k < 8; k++) {
            const uint32_t kb = (uint32_t)k * 32u;
            uint32_t a0, a1, a2, a3, a4, a5, a6, a7;
            uint32_t h0, h1, h2, h3, h4, h5, h6, h7;
            ldm_x4(aB + kb, a0, a1, a2, a3);
            ldm_x4(aB + 16 * 528 + kb, a4, a5, a6, a7);
            ldm_x4(bB + kb, h0, h1, h2, h3);
            ldm_x4(bB + 16 * 528 + kb, h4, h5, h6, h7);
            MMA16816(acc[0][0], a0, a1, a2, a3, h0, h1);
            MMA16816(acc[0][1], a0, a1, a2, a3, h2, h3);
            MMA16816(acc[0][2], a0, a1, a2, a3, h4, h5);
            MMA16816(acc[0][3], a0, a1, a2, a3, h6, h7);
            MMA16816(acc[1][0], a4, a5, a6, a7, h0, h1);
            MMA16816(acc[1][1], a4, a5, a6, a7, h2, h3);
            MMA16816(acc[1][2], a4, a5, a6, a7, h4, h5);
            MMA16816(acc[1][3], a4, a5, a6, a7, h6, h7);
        }

        if (wk == 0) {
#pragma unroll
            for (int mi = 0; mi < 2; mi++) {
                const int row = 256 + wm1 * 32 + mi * 16 + (lane >> 2);
#pragma unroll
                for (int nf = 0; nf < 4; nf++) {
                    const int col = wn1 * 32 + nf * 8 + (lane & 3) * 2;
                    scp[row * 65 + col]           = acc[mi][nf][0];
                    scp[row * 65 + col + 1]       = acc[mi][nf][1];
                    scp[(row + 8) * 65 + col]     = acc[mi][nf][2];
                    scp[(row + 8) * 65 + col + 1] = acc[mi][nf][3];
                }
            }
        }
        __syncthreads();   // all W/A ldmatrix done -> W region reusable

        // prefetch X chunk 0 into retired W region (overlaps wk1 merge + epilogue)
        for (int idx = tid; idx < 2048; idx += 256) {
            int r = idx >> 4, cb = idx & 15;
            cp16(sb + OFF_XW + r * 272 + cb * 16, g_X4 + (((size_t)(j * 256 + r)) * 48) + cb);
        }
        CP_COMMIT();

        if (wk == 1) {
#pragma unroll
            for (int mi = 0; mi < 2; mi++) {
                const int row = 256 + wm1 * 32 + mi * 16 + (lane >> 2);
#pragma unroll
                for (int nf = 0; nf < 4; nf++) {
                    const int col = wn1 * 32 + nf * 8 + (lane & 3) * 2;
                    scp[row * 65 + col]           += acc[mi][nf][0];
                    scp[row * 65 + col + 1]       += acc[mi][nf][1];
                    scp[(row + 8) * 65 + col]     += acc[mi][nf][2];
                    scp[(row + 8) * 65 + col + 1] += acc[mi][nf][3];
                }
            }
        }
    }
    __syncthreads();

    // ===== epilogue: softmaxes, den/num, e -> smem bf16 (s < 304) =====
    for (int r = tid; r < 320; r += 256) {
#pragma unroll
        for (int h = 0; h < 2; h++) {
            float m = -FLT_MAX;
            for (int t = 0; t < 32; t++) m = fmaxf(m, scp[r * 65 + h * 32 + t]);
            float s = 0.f;
            for (int t = 0; t < 32; t++) s += __expf(scp[r * 65 + h * 32 + t] - m);
            rmaxp[r * 2 + h] = m;
            rinvp[r * 2 + h] = 1.f / s;
        }
    }
    __syncthreads();
    {
        const int t = tid & 63, sg = tid >> 6, h = t >> 5;
        float dpart = 0.f, npart = 0.f;
        __nv_bfloat16* eP = (__nv_bfloat16*)(sm + OFF_E);
        for (int k2 = 0; k2 < 76; k2++) {
            const int s = sg * 76 + k2;   // covers s < 304
            float e = 0.f;
            if (s < Sn) {
                float sv = scp[s * 65 + t];
                float a1 = __expf(sv - rmaxp[s * 2 + h]) * rinvp[s * 2 + h];
                e = __expf(G1f * a1);
                dpart += e;
                npart += e * sv;
            }
            eP[t * 392 + s] = __float2bfloat16(e);
        }
        atomicAdd(&denA[t], dpart);
        atomicAdd(&numA[t], npart);
    }
    __syncthreads();   // scp consumed; X buffers may overwrite it

    // ===== phase 2: wC = X @ e^T; K = 304; chunks {128,128,48} x 2 m-tiles =====
    {
        const int wm2 = w >> 1;
        const int wn2 = w & 1;
        const uint32_t bRow2 = 32u * wn2 + (((uint32_t)lane >> 4) << 3) + (lane & 7);

        float acc2[2][4][4];
        for (int q = 0; q < 6; q++) {
            const int sc3 = q % 3;
            const uint32_t xb = (q == 0) ? (sb + OFF_XW)
                              : (sb + ((q & 1) ? OFF_XB0 : OFF_XB1));
            if (q + 1 < 6) {
                const int mtn = (q + 1) / 3, sc3n = (q + 1) % 3;
                uint32_t dst = sb + (((q + 1) & 1) ? OFF_XB0 : OFF_XB1);
                if (sc3n < 2) {
                    for (int idx = tid; idx < 2048; idx += 256) {
                        int r = idx >> 4, cb = idx & 15;
                        cp16(dst + r * 272 + cb * 16,
                             g_X4 + (((size_t)(j * 256 + mtn * 128 + r)) * 48) + sc3n * 16 + cb);
                    }
                } else {
                    for (int idx = tid; idx < 768; idx += 256) {
                        int r = idx / 6, cb = idx % 6;
                        cp16(dst + r * 272 + cb * 16,
                             g_X4 + (((size_t)(j * 256 + mtn * 128 + r)) * 48) + 32 + cb);
                    }
                }
                CP_COMMIT();
                CP_WAIT1();
            } else {
                CP_WAIT0();
            }
            __syncthreads();

            if (sc3 == 0) {
#pragma unroll
                for (int mi = 0; mi < 2; mi++)
#pragma unroll
                    for (int n = 0; n < 4; n++)
#pragma unroll
                        for (int r = 0; r < 4; r++) acc2[mi][n][r] = 0.f;
            }

            const uint32_t eB0 = sb + OFF_E + bRow2 * 784 + (uint32_t)sc3 * 256u + boffB;
            const uint32_t eB1 = eB0 + 16 * 784;
            const uint32_t xA  = xb + (wm2 * 32 + rowA) * 272 + coffA;

            const int kmax = (sc3 == 2) ? 3 : 8;
#pragma unroll 4
            for (int k = 0; k < kmax; k++) {
                const uint32_t kb = (uint32_t)k * 32u;
                uint32_t x0, x1, x2, x3, x4, x5, x6, x7;
                uint32_t e0, e1, e2, e3, e4, e5, e6, e7;
                ldm_x4(xA + kb, x0, x1, x2, x3);
                ldm_x4(xA + 16 * 272 + kb, x4, x5, x6, x7);
                ldm_x4(eB0 + kb, e0, e1, e2, e3);
                ldm_x4(eB1 + kb, e4, e5, e6, e7);
                MMA16816(acc2[0][0], x0, x1, x2, x3, e0, e1);
                MMA16816(acc2[0][1], x0, x1, x2, x3, e2, e3);
                MMA16816(acc2[0][2], x0, x1, x2, x3, e4, e5);
                MMA16816(acc2[0][3], x0, x1, x2, x3, e6, e7);
                MMA16816(acc2[1][0], x4, x5, x6, x7, e0, e1);
                MMA16816(acc2[1][1], x4, x5, x6, x7, e2, e3);
                MMA16816(acc2[1][2], x4, x5, x6, x7, e4, e5);
                MMA16816(acc2[1][3], x4, x5, x6, x7, e6, e7);
            }
            __syncthreads();   // xb fully consumed

            if (sc3 == 2) {
#pragma unroll
                for (int n = 0; n < 4; n++) {
                    float v0 = 0.f, v1 = 0.f;
#pragma unroll
                    for (int mi = 0; mi < 2; mi++) {
                        v0 += acc2[mi][n][0] * acc2[mi][n][0] + acc2[mi][n][2] * acc2[mi][n][2];
                        v1 += acc2[mi][n][1] * acc2[mi][n][1] + acc2[mi][n][3] * acc2[mi][n][3];
                    }
#pragma unroll
                    for (int o = 4; o <= 16; o <<= 1) {
                        v0 += __shfl_xor_sync(0xffffffffu, v0, o);
                        v1 += __shfl_xor_sync(0xffffffffu, v1, o);
                    }
                    if (lane < 4) {
                        const int t = (4 * wn2 + n) * 8 + lane * 2;
                        atomicAdd(&wn2A[t], v0);
                        atomicAdd(&wn2A[t + 1], v1);
                    }
                }
            }
        }
    }
    __syncthreads();

    if (tid < 64) {
        const int t = tid;
        float dinv = 1.f / denA[t];
        float wnv = sqrtf(wn2A[t]) * dinv;
        float nm = numA[t] * dinv;
        float qnv = g_qn[ip * 64 + t];
        float cosv = nm / fmaxf(qnv * wnv, EPSf);
        float v = G2f * cosv;
        float m = v;
        for (int o = 16; o; o >>= 1) m = fmaxf(m, __shfl_xor_sync(0xffffffffu, m, o));
        float e = __expf(v - m);
        for (int o = 16; o; o >>= 1) e += __shfl_xor_sync(0xffffffffu, e, o);
        if (lane == 0) g_simT[j * 64 + ip * 2 + (tid >> 5)] = logf(e) + m;
    }
}

// ---------------- moco GEMM with fused per-block LSE ----------------
__global__ void __launch_bounds__(256) moco_gemm_kernel(const float* __restrict__ queue,
                                                        const float* __restrict__ queue_im) {
    int k0 = blockIdx.x * 64;
    int d = blockIdx.y;
    const float* A = g_codes[d];
    const float* Q = (d == 0) ? queue : queue_im;
    __shared__ float sA[64 * 33];
    __shared__ float sB[32 * 65];
    int tid = threadIdx.x;
    int rg = tid >> 4;
    int kg = tid & 15;
    float acc[4][4];
#pragma unroll
    for (int u = 0; u < 4; u++)
#pragma unroll
        for (int v = 0; v < 4; v++) acc[u][v] = 0.f;
    for (int c0 = 0; c0 < NEFc; c0 += 32) {
        __syncthreads();
        for (int idx = tid; idx < 64 * 32; idx += 256) {
            int r = idx >> 5, cc = idx & 31;
            sA[r * 33 + cc] = A[r * NEFc + c0 + cc];
        }
        for (int idx = tid; idx < 32 * 64; idx += 256) {
            int cc = idx >> 6, kk = idx & 63;
            sB[cc * 65 + kk] = Q[(size_t)(c0 + cc) * Kq + k0 + kk];
        }
        __syncthreads();
#pragma unroll 4
        for (int cc = 0; cc < 32; cc++) {
            float a0 = sA[(rg * 4 + 0) * 33 + cc];
            float a1 = sA[(rg * 4 + 1) * 33 + cc];
            float a2 = sA[(rg * 4 + 2) * 33 + cc];
            float a3 = sA[(rg * 4 + 3) * 33 + cc];
#pragma unroll
            for (int v = 0; v < 4; v++) {
                float b = sB[cc * 65 + kg + 16 * v];
                acc[0][v] += a0 * b;
                acc[1][v] += a1 * b;
                acc[2][v] += a2 * b;
                acc[3][v] += a3 * b;
            }
        }
    }
#pragma unroll
    for (int u = 0; u < 4; u++) {
        float z0 = acc[u][0] * INV_T, z1 = acc[u][1] * INV_T;
        float z2 = acc[u][2] * INV_T, z3 = acc[u][3] * INV_T;
        float m = fmaxf(fmaxf(z0, z1), fmaxf(z2, z3));
        float s = __expf(z0 - m) + __expf(z1 - m) + __expf(z2 - m) + __expf(z3 - m);
#pragma unroll
        for (int o = 1; o < 16; o <<= 1) {
            float om = __shfl_xor_sync(0xffffffffu, m, o);
            float os = __shfl_xor_sync(0xffffffffu, s, o);
            float nm = fmaxf(m, om);
            s = s * __expf(m - nm) + os * __expf(om - nm);
            m = nm;
        }
        if (kg == 0) {
            g_part[d][rg * 4 + u][blockIdx.x][0] = m;
            g_part[d][rg * 4 + u][blockIdx.x][1] = s;
        }
    }
}

// ---------------- pair GEMMs: grid (16, 2), 4x64 tile per block ----------------
#define K5_SMEM ((64 * 257 + 4 * 256) * 4)
__global__ void __launch_bounds__(256) pair_gemm_kernel() {
    const int rb = blockIdx.x, d = blockIdx.y;
    const float* A  = g_codes[(d == 0) ? 0 : 1];
    const float* Bm = g_codes[(d == 0) ? 1 : 3];
    extern __shared__ float sh2[];
    float* shB = sh2;              // [64][257]
    float* shA = sh2 + 64 * 257;   // [4][256]
    const int tid = threadIdx.x;
    for (int idx = tid; idx < 64 * 256; idx += 256) {
        int r = idx >> 8, c = idx & 255;
        shB[r * 257 + c] = Bm[idx];
    }
    for (int idx = tid; idx < 4 * 256; idx += 256)
        shA[idx] = A[rb * 4 * 256 + idx];
    __syncthreads();
    const int u = tid >> 6, v = tid & 63;
    float s = 0.f;
#pragma unroll 8
    for (int k = 0; k < 256; k++)
        s += shA[u * 256 + k] * shB[v * 257 + k];
    g_small[d][(rb * 4 + u) * 64 + v] = G3f * s;
}

__device__ float lse_md_row(const float* M, int r, float scale) {
    float mx = -FLT_MAX;
    for (int c2 = 0; c2 < 64; c2++) mx = fmaxf(mx, scale * M[r * 64 + c2]);
    float s = 0.f;
    for (int c2 = 0; c2 < 64; c2++) s += __expf(scale * M[r * 64 + c2] - mx);
    return logf(s) + mx - scale * M[r * 64 + r];
}
__device__ float lse_md_col(const float* M, int c2, float scale) {
    float mx = -FLT_MAX;
    for (int r = 0; r < 64; r++) mx = fmaxf(mx, scale * M[r * 64 + c2]);
    float s = 0.f;
    for (int r = 0; r < 64; r++) s += __expf(scale * M[r * 64 + c2] - mx);
    return logf(s) + mx - scale * M[c2 * 64 + c2];
}

__global__ void __launch_bounds__(1024) finalize_kernel(float* __restrict__ out) {
    __shared__ float sv[8][64];
    const int tid = threadIdx.x, lane = tid & 31;
    // moco merge: 128 (d,i) pairs x 8 subs; each sub merges 32 partials
    {
        const int pair = tid >> 3, sub = tid & 7;
        const int d = pair >> 6, i = pair & 63;
        float M = -FLT_MAX, S = 0.f;
        for (int b = sub * 32; b < sub * 32 + 32; b++) {
            float m = g_part[d][i][b][0], s = g_part[d][i][b][1];
            float nm = fmaxf(M, m);
            S = S * __expf(M - nm) + s * __expf(m - nm);
            M = nm;
        }
        // combine 8 subs (lanes pair*8..pair*8+7 within warp)
#pragma unroll
        for (int o = 1; o < 8; o <<= 1) {
            float oM = __shfl_xor_sync(0xffffffffu, M, o);
            float oS = __shfl_xor_sync(0xffffffffu, S, o);
            float nm = fmaxf(M, oM);
            S = S * __expf(M - nm) + oS * __expf(oM - nm);
            M = nm;
        }
        if (sub == 0) {
            float pos = 0.f;
            const float* a = g_codes[d];
            const float* b2 = g_codes[(d == 0) ? 3 : 2];
            for (int k = 0; k < NEFc; k++) pos += a[i * NEFc + k] * b2[i * NEFc + k];
            pos *= INV_T;
            float Mf = fmaxf(pos, M);
            float Sf = __expf(pos - Mf) + S * __expf(M - Mf);
            sv[6 + d][i] = logf(Sf) + Mf - pos;
        }
    }
    // lse tasks: one per thread (384 tasks)
    if (tid < 384) {
        const int kind = tid >> 6, i = tid & 63;
        float r;
        switch (kind) {
            case 0: r = lse_md_row(g_simT, i, G3f); break;
            case 1: r = lse_md_col(g_simT, i, G3f); break;
            case 2: r = lse_md_row(g_small[0], i, 1.f); break;
            case 3: r = lse_md_col(g_small[0], i, 1.f); break;
            case 4: r = lse_md_row(g_small[1], i, 1.f); break;
            default: r = lse_md_col(g_small[1], i, 1.f); break;
        }
        if (kind < 5) sv[kind][i] = r; else sv[5][i] = r;
    }
    __syncthreads();
    if (tid == 0) {
        float a[8];
        for (int q2 = 0; q2 < 8; q2++) {
            float s = 0.f;
            for (int k = 0; k < 64; k++) s += sv[q2][k];
            a[q2] = s * (1.f / 64.f);
        }
        out[0] = a[0];
        out[1] = a[1];
        out[2] = a[2];
        out[3] = a[3];
        out[4] = 0.5f * (a[6] + a[7]);
        out[5] = a[4];
        out[6] = a[5];
    }
    (void)lane;
}

extern "C" void kernel_launch(void* const* d_in, const int* in_sizes, int n_in,
                              void* d_out, int out_size) {
    const float* cnn      = (const float*)d_in[0];
    const float* rnn      = (const float*)d_in[1];
    const float* imgf     = (const float*)d_in[2];
    const float* we       = (const float*)d_in[3];
    const float* cnn_aug  = (const float*)d_in[4];
    const float* rnn_aug  = (const float*)d_in[5];
    const float* queue    = (const float*)d_in[6];
    const float* queue_im = (const float*)d_in[7];
    float* out = (float*)d_out;

    cudaFuncSetAttribute(prep_AX, cudaFuncAttributeMaxDynamicSharedMemorySize, PAX_SMEM);
    cudaFuncSetAttribute(word_mma_kernel, cudaFuncAttributeMaxDynamicSharedMemorySize, WK_SMEM);
    cudaFuncSetAttribute(pair_gemm_kernel, cudaFuncAttributeMaxDynamicSharedMemorySize, K5_SMEM);

    prep_AX<<<dim3(64, 4), 256, PAX_SMEM>>>(imgf);                       // 1
    prep_B<<<2048, 256>>>(we);                                           // 2
    normalize_kernel<<<dim3(64, 4), 256>>>(cnn, rnn, cnn_aug, rnn_aug);  // 3
    word_mma_kernel<<<2048, 256, WK_SMEM>>>();                           // 4  <- ncu capture slot
    moco_gemm_kernel<<<dim3(256, 2), 256>>>(queue, queue_im);            // 5
    pair_gemm_kernel<<<dim3(16, 2), 256, K5_SMEM>>>();                   // 6
    finalize_kernel<<<1, 1024>>>(out);                                   // 7
}

// round 15
// speedup vs baseline: 1.2799x; 1.0280x over previous
#include <cuda_runtime.h>
#include <cuda_bf16.h>
#include <math.h>
#include <float.h>
#include <stdint.h>

#define Bn   64
#define Tn   32
#define NEFc 256
#define Sn   289
#define SPAD 384
#define S2   304
#define Kq   16384
#define G1f  4.0f
#define G2f  5.0f
#define G3f  10.0f
#define INV_T 20.0f
#define EPSf 1e-8f

// ---------------- device scratch (bf16 single precision copies) ----------------
__device__ uint4 g_A4[64 * SPAD * 256 / 8];   // ctxT [j][s_pad][c] bf16
__device__ uint4 g_X4[64 * 256 * SPAD / 8];   // imgf [j][c][s_pad] bf16
__device__ uint4 g_B4[2048 * 256 / 8];        // we   [i*32+t][c] bf16
__device__ float g_qn[2048];
__device__ float g_codes[4][Bn * NEFc];
__device__ float g_simT[Bn * Bn];
__device__ float g_part[2][Bn][256][2];       // moco per-kblock (max, sumexp)
__device__ float g_small[2][Bn * Bn];

// ---------------- helpers ----------------
__device__ __forceinline__ uint32_t smem_u32(const void* p) {
    uint32_t a;
    asm("{ .reg .u64 t; cvta.to.shared.u64 t, %1; cvt.u32.u64 %0, t; }" : "=r"(a) : "l"(p));
    return a;
}
__device__ __forceinline__ void ldm_x4(uint32_t addr, uint32_t& r0, uint32_t& r1, uint32_t& r2, uint32_t& r3) {
    asm volatile("ldmatrix.sync.aligned.m8n8.x4.shared.b16 {%0,%1,%2,%3}, [%4];"
                 : "=r"(r0), "=r"(r1), "=r"(r2), "=r"(r3) : "r"(addr));
}
#define MMA16816(d, A0, A1, A2, A3, B0, B1)                                   \
    asm volatile("mma.sync.aligned.m16n8k16.row.col.f32.bf16.bf16.f32 "       \
                 "{%0,%1,%2,%3},{%4,%5,%6,%7},{%8,%9},{%0,%1,%2,%3};"          \
                 : "+f"((d)[0]), "+f"((d)[1]), "+f"((d)[2]), "+f"((d)[3])      \
                 : "r"(A0), "r"(A1), "r"(A2), "r"(A3), "r"(B0), "r"(B1))

__device__ __forceinline__ void cp16(uint32_t s, const void* g) {
    asm volatile("cp.async.ca.shared.global [%0], [%1], 16;" :: "r"(s), "l"(g));
}
#define CP_COMMIT() asm volatile("cp.async.commit_group;" ::: "memory")
#define CP_WAIT0()  asm volatile("cp.async.wait_group 0;" ::: "memory")
#define CP_WAIT1()  asm volatile("cp.async.wait_group 1;" ::: "memory")

// ---------------- prep_AX (vectorized) ----------------
#define PAX_SMEM (64 * 385 * 4)
__global__ void __launch_bounds__(256) prep_AX(const float* __restrict__ imgf) {
    const int j = blockIdx.x, ct = blockIdx.y;
    extern __shared__ float tile[];
    const int tid = threadIdx.x;
    // flat contiguous 64x289 block, 16B aligned: float4 loads
    const float4* src4 = (const float4*)(imgf + ((size_t)j * 256 + ct * 64) * Sn);
    for (int idx = tid; idx < 4624; idx += 256) {
        float4 v = src4[idx];
        int f = idx * 4;
        int r0 = f / Sn, s0 = f - r0 * Sn;
        tile[r0 * 385 + s0] = v.x;
        int f1 = f + 1; int r1 = f1 / Sn, s1 = f1 - r1 * Sn;
        tile[r1 * 385 + s1] = v.y;
        int f2 = f + 2; int r2 = f2 / Sn, s2 = f2 - r2 * Sn;
        tile[r2 * 385 + s2] = v.z;
        int f3 = f + 3; int r3 = f3 / Sn, s3 = f3 - r3 * Sn;
        tile[r3 * 385 + s3] = v.w;
    }
    __syncthreads();
    // A: [s][c] c contiguous; 8 bf16 per store
    for (int idx = tid; idx < SPAD * 8; idx += 256) {
        const int s = idx >> 3, cg = idx & 7;
        uint4 o;
        __nv_bfloat16* ob = (__nv_bfloat16*)&o;
#pragma unroll
        for (int u = 0; u < 8; u++) {
            float v = (s < Sn) ? tile[(cg * 8 + u) * 385 + s] : 0.f;
            ob[u] = __float2bfloat16(v);
        }
        *(uint4*)(((__nv_bfloat16*)g_A4) + ((size_t)j * SPAD + s) * 256 + ct * 64 + cg * 8) = o;
    }
    // X: [c][s] s contiguous; 8 bf16 per store (s < 304)
    for (int idx = tid; idx < 64 * 38; idx += 256) {
        const int c = idx / 38, sg = idx - c * 38;
        const int s0 = sg * 8;
        uint4 o;
        __nv_bfloat16* ob = (__nv_bfloat16*)&o;
#pragma unroll
        for (int u = 0; u < 8; u++) {
            int s = s0 + u;
            float v = (s < Sn) ? tile[c * 385 + s] : 0.f;
            ob[u] = __float2bfloat16(v);
        }
        *(uint4*)(((__nv_bfloat16*)g_X4) + ((size_t)j * 256 + ct * 64 + c) * SPAD + s0) = o;
    }
}

__global__ void prep_B(const float* __restrict__ we) {
    int r = blockIdx.x, c = threadIdx.x;
    float v = we[(size_t)r * 256 + c];
    ((__nv_bfloat16*)g_B4)[(size_t)r * 256 + c] = __float2bfloat16(v);
    __shared__ float red[8];
    float s = v * v;
    for (int o = 16; o; o >>= 1) s += __shfl_down_sync(0xffffffffu, s, o);
    if ((c & 31) == 0) red[c >> 5] = s;
    __syncthreads();
    if (c == 0) {
        float tot = 0.f;
#pragma unroll
        for (int w = 0; w < 8; w++) tot += red[w];
        g_qn[r] = sqrtf(tot);
    }
}

__global__ void normalize_kernel(const float* __restrict__ c0, const float* __restrict__ c1,
                                 const float* __restrict__ c2, const float* __restrict__ c3) {
    int i = blockIdx.x;
    int m = blockIdx.y;
    const float* src = (m == 0) ? c0 : (m == 1) ? c1 : (m == 2) ? c2 : c3;
    int tid = threadIdx.x;
    __shared__ float red[8];
    float v = src[i * NEFc + tid];
    float s = v * v;
    for (int o = 16; o; o >>= 1) s += __shfl_down_sync(0xffffffffu, s, o);
    if ((tid & 31) == 0) red[tid >> 5] = s;
    __syncthreads();
    float tot = 0.f;
#pragma unroll
    for (int w = 0; w < 8; w++) tot += red[w];
    g_codes[m][i * NEFc + tid] = v / fmaxf(sqrtf(tot), EPSf);
}

// ---------------- word kernel smem layout (bytes) ----------------
#define OFF_SC   0
#define OFF_W    83200
#define OFF_AB   116992
#define OFF_XW   83200
#define OFF_E    118016
#define OFF_XB0  0
#define OFF_XB1  34816
#define OFF_DEN  184576
#define OFF_NUM  184832
#define OFF_WN2  185088
#define OFF_RMAX 185344
#define OFF_RINV 187904
#define WK_SMEM  190464

__global__ void __launch_bounds__(256, 1) word_mma_kernel() {
    const int j  = blockIdx.x >> 5;
    const int ip = blockIdx.x & 31;
    extern __shared__ char sm[];
    const uint32_t sb = smem_u32(sm);
    const int tid = threadIdx.x, lane = tid & 31, w = tid >> 5;

    float* scp   = (float*)(sm + OFF_SC);
    float* denA  = (float*)(sm + OFF_DEN);
    float* numA  = (float*)(sm + OFF_NUM);
    float* wn2A  = (float*)(sm + OFF_WN2);
    float* rmaxp = (float*)(sm + OFF_RMAX);
    float* rinvp = (float*)(sm + OFF_RINV);
    if (tid < 192) denA[tid] = 0.f;

    for (int idx = tid; idx < 2048; idx += 256) {
        int r = idx >> 5, cb = idx & 31;
        cp16(sb + OFF_W + r * 528 + cb * 16, g_B4 + (((size_t)(ip * 64 + r)) << 5) + cb);
    }
    for (int idx = tid; idx < 4096; idx += 256) {
        int r = idx >> 5, cb = idx & 31;
        cp16(sb + OFF_AB + r * 528 + cb * 16, g_A4 + (((size_t)j * SPAD + r) << 5) + cb);
    }
    CP_COMMIT();

    const uint32_t rowA  = (lane & 7) + ((lane >> 3) & 1) * 8;
    const uint32_t coffA = (lane >> 4) * 16;
    const uint32_t boffB = ((lane >> 3) & 1) * 16;

    // ===== phase 1a =====
    {
        const int wm = w >> 1;
        const int wn = w & 1;
        const uint32_t bRow = 32u * wn + (((uint32_t)lane >> 4) << 3) + (lane & 7);
        const uint32_t bB = sb + OFF_W + bRow * 528 + boffB;

        for (int ch = 0; ch < 2; ch++) {
            CP_WAIT0();
            __syncthreads();

            float acc[2][4][4];
#pragma unroll
            for (int mi = 0; mi < 2; mi++)
#pragma unroll
                for (int nf = 0; nf < 4; nf++)
#pragma unroll
                    for (int r = 0; r < 4; r++) acc[mi][nf][r] = 0.f;

            const uint32_t aB = sb + OFF_AB + (wm * 32 + rowA) * 528 + coffA;

#pragma unroll 4
            for (int k = 0; k < 16; k++) {
                const uint32_t kb = (uint32_t)k * 32u;
                uint32_t a0, a1, a2, a3, a4, a5, a6, a7;
                uint32_t h0, h1, h2, h3, h4, h5, h6, h7;
                ldm_x4(aB + kb, a0, a1, a2, a3);
                ldm_x4(aB + 16 * 528 + kb, a4, a5, a6, a7);
                ldm_x4(bB + kb, h0, h1, h2, h3);
                ldm_x4(bB + 16 * 528 + kb, h4, h5, h6, h7);
                MMA16816(acc[0][0], a0, a1, a2, a3, h0, h1);
                MMA16816(acc[0][1], a0, a1, a2, a3, h2, h3);
                MMA16816(acc[0][2], a0, a1, a2, a3, h4, h5);
                MMA16816(acc[0][3], a0, a1, a2, a3, h6, h7);
                MMA16816(acc[1][0], a4, a5, a6, a7, h0, h1);
                MMA16816(acc[1][1], a4, a5, a6, a7, h2, h3);
                MMA16816(acc[1][2], a4, a5, a6, a7, h4, h5);
                MMA16816(acc[1][3], a4, a5, a6, a7, h6, h7);
            }
            __syncthreads();

            if (ch == 0) {
                for (int idx = tid; idx < 4096; idx += 256) {
                    int r = idx >> 5, cb = idx & 31;
                    cp16(sb + OFF_AB + r * 528 + cb * 16,
                         g_A4 + (((size_t)j * SPAD + 128 + r) << 5) + cb);
                }
                CP_COMMIT();
            } else {
                for (int idx = tid; idx < 2048; idx += 256) {
                    int r = idx >> 5, cb = idx & 31;
                    cp16(sb + OFF_AB + r * 528 + cb * 16,
                         g_A4 + (((size_t)j * SPAD + 256 + r) << 5) + cb);
                }
                CP_COMMIT();
            }

#pragma unroll
            for (int mi = 0; mi < 2; mi++) {
                const int row = ch * 128 + wm * 32 + mi * 16 + (lane >> 2);
#pragma unroll
                for (int nf = 0; nf < 4; nf++) {
                    const int col = wn * 32 + nf * 8 + (lane & 3) * 2;
                    scp[row * 65 + col]           = acc[mi][nf][0];
                    scp[row * 65 + col + 1]       = acc[mi][nf][1];
                    scp[(row + 8) * 65 + col]     = acc[mi][nf][2];
                    scp[(row + 8) * 65 + col + 1] = acc[mi][nf][3];
                }
            }
        }
    }

    // ===== phase 1b: tail =====
    {
        const int wk  = w >> 2;
        const int wm1 = (w >> 1) & 1;
        const int wn1 = w & 1;
        const uint32_t bRow1 = 32u * wn1 + (((uint32_t)lane >> 4) << 3) + (lane & 7);

        CP_WAIT0();
        __syncthreads();

        float acc[2][4][4];
#pragma unroll
        for (int mi = 0; mi < 2; mi++)
#pragma unroll
            for (int nf = 0; nf < 4; nf++)
#pragma unroll
                for (int r = 0; r < 4; r++) acc[mi][nf][r] = 0.f;

        const uint32_t aB = sb + OFF_AB + (wm1 * 32 + rowA) * 528 + coffA + (uint32_t)wk * 256u;
        const uint32_t bB = sb + OFF_W + bRow1 * 528 + boffB + (uint32_t)wk * 256u;

#pragma unroll
        for (int k = 0; k < 8; k++) {
            const uint32_t kb = (uint32_t)k * 32u;
            uint32_t a0, a1, a2, a3, a4, a5, a6, a7;
            uint32_t h0, h1, h2, h3, h4, h5, h6, h7;
            ldm_x4(aB + kb, a0, a1, a2, a3);
            ldm_x4(aB + 16 * 528 + kb, a4, a5, a6, a7);
            ldm_x4(bB + kb, h0, h1, h2, h3);
            ldm_x4(bB + 16 * 528 + kb, h4, h5, h6, h7);
            MMA16816(acc[0][0], a0, a1, a2, a3, h0, h1);
            MMA16816(acc[0][1], a0, a1, a2, a3, h2, h3);
            MMA16816(acc[0][2], a0, a1, a2, a3, h4, h5);
            MMA16816(acc[0][3], a0, a1, a2, a3, h6, h7);
            MMA16816(acc[1][0], a4, a5, a6, a7, h0, h1);
            MMA16816(acc[1][1], a4, a5, a6, a7, h2, h3);
            MMA16816(acc[1][2], a4, a5, a6, a7, h4, h5);
            MMA16816(acc[1][3], a4, a5, a6, a7, h6, h7);
        }

        if (wk == 0) {
#pragma unroll
            for (int mi = 0; mi < 2; mi++) {
                const int row = 256 + wm1 * 32 + mi * 16 + (lane >> 2);
#pragma unroll
                for (int nf = 0; nf < 4; nf++) {
                    const int col = wn1 * 32 + nf * 8 + (lane & 3) * 2;
                    scp[row * 65 + col]           = acc[mi][nf][0];
                    scp[row * 65 + col + 1]       = acc[mi][nf][1];
                    scp[(row + 8) * 65 + col]     = acc[mi][nf][2];
                    scp[(row + 8) * 65 + col + 1] = acc[mi][nf][3];
                }
            }
        }
        __syncthreads();

        for (int idx = tid; idx < 2048; idx += 256) {
            int r = idx >> 4, cb = idx & 15;
            cp16(sb + OFF_XW + r * 272 + cb * 16, g_X4 + (((size_t)(j * 256 + r)) * 48) + cb);
        }
        CP_COMMIT();

        if (wk == 1) {
#pragma unroll
            for (int mi = 0; mi < 2; mi++) {
                const int row = 256 + wm1 * 32 + mi * 16 + (lane >> 2);
#pragma unroll
                for (int nf = 0; nf < 4; nf++) {
                    const int col = wn1 * 32 + nf * 8 + (lane & 3) * 2;
                    scp[row * 65 + col]           += acc[mi][nf][0];
                    scp[row * 65 + col + 1]       += acc[mi][nf][1];
                    scp[(row + 8) * 65 + col]     += acc[mi][nf][2];
                    scp[(row + 8) * 65 + col + 1] += acc[mi][nf][3];
                }
            }
        }
    }
    __syncthreads();

    // ===== epilogue =====
    for (int r = tid; r < 320; r += 256) {
#pragma unroll
        for (int h = 0; h < 2; h++) {
            float m = -FLT_MAX;
            for (int t = 0; t < 32; t++) m = fmaxf(m, scp[r * 65 + h * 32 + t]);
            float s = 0.f;
            for (int t = 0; t < 32; t++) s += __expf(scp[r * 65 + h * 32 + t] - m);
            rmaxp[r * 2 + h] = m;
            rinvp[r * 2 + h] = 1.f / s;
        }
    }
    __syncthreads();
    {
        const int t = tid & 63, sg = tid >> 6, h = t >> 5;
        float dpart = 0.f, npart = 0.f;
        __nv_bfloat16* eP = (__nv_bfloat16*)(sm + OFF_E);
        for (int k2 = 0; k2 < 76; k2++) {
            const int s = sg * 76 + k2;
            float e = 0.f;
            if (s < Sn) {
                float sv = scp[s * 65 + t];
                float a1 = __expf(sv - rmaxp[s * 2 + h]) * rinvp[s * 2 + h];
                e = __expf(G1f * a1);
                dpart += e;
                npart += e * sv;
            }
            eP[t * 392 + s] = __float2bfloat16(e);
        }
        atomicAdd(&denA[t], dpart);
        atomicAdd(&numA[t], npart);
    }
    __syncthreads();

    // ===== phase 2 =====
    {
        const int wm2 = w >> 1;
        const int wn2 = w & 1;
        const uint32_t bRow2 = 32u * wn2 + (((uint32_t)lane >> 4) << 3) + (lane & 7);

        float acc2[2][4][4];
        for (int q = 0; q < 6; q++) {
            const int sc3 = q % 3;
            const uint32_t xb = (q == 0) ? (sb + OFF_XW)
                              : (sb + ((q & 1) ? OFF_XB0 : OFF_XB1));
            if (q + 1 < 6) {
                const int mtn = (q + 1) / 3, sc3n = (q + 1) % 3;
                uint32_t dst = sb + (((q + 1) & 1) ? OFF_XB0 : OFF_XB1);
                if (sc3n < 2) {
                    for (int idx = tid; idx < 2048; idx += 256) {
                        int r = idx >> 4, cb = idx & 15;
                        cp16(dst + r * 272 + cb * 16,
                             g_X4 + (((size_t)(j * 256 + mtn * 128 + r)) * 48) + sc3n * 16 + cb);
                    }
                } else {
                    for (int idx = tid; idx < 768; idx += 256) {
                        int r = idx / 6, cb = idx % 6;
                        cp16(dst + r * 272 + cb * 16,
                             g_X4 + (((size_t)(j * 256 + mtn * 128 + r)) * 48) + 32 + cb);
                    }
                }
                CP_COMMIT();
                CP_WAIT1();
            } else {
                CP_WAIT0();
            }
            __syncthreads();

            if (sc3 == 0) {
#pragma unroll
                for (int mi = 0; mi < 2; mi++)
#pragma unroll
                    for (int n = 0; n < 4; n++)
#pragma unroll
                        for (int r = 0; r < 4; r++) acc2[mi][n][r] = 0.f;
            }

            const uint32_t eB0 = sb + OFF_E + bRow2 * 784 + (uint32_t)sc3 * 256u + boffB;
            const uint32_t eB1 = eB0 + 16 * 784;
            const uint32_t xA  = xb + (wm2 * 32 + rowA) * 272 + coffA;

            const int kmax = (sc3 == 2) ? 3 : 8;
#pragma unroll 4
            for (int k = 0; k < kmax; k++) {
                const uint32_t kb = (uint32_t)k * 32u;
                uint32_t x0, x1, x2, x3, x4, x5, x6, x7;
                uint32_t e0, e1, e2, e3, e4, e5, e6, e7;
                ldm_x4(xA + kb, x0, x1, x2, x3);
                ldm_x4(xA + 16 * 272 + kb, x4, x5, x6, x7);
                ldm_x4(eB0 + kb, e0, e1, e2, e3);
                ldm_x4(eB1 + kb, e4, e5, e6, e7);
                MMA16816(acc2[0][0], x0, x1, x2, x3, e0, e1);
                MMA16816(acc2[0][1], x0, x1, x2, x3, e2, e3);
                MMA16816(acc2[0][2], x0, x1, x2, x3, e4, e5);
                MMA16816(acc2[0][3], x0, x1, x2, x3, e6, e7);
                MMA16816(acc2[1][0], x4, x5, x6, x7, e0, e1);
                MMA16816(acc2[1][1], x4, x5, x6, x7, e2, e3);
                MMA16816(acc2[1][2], x4, x5, x6, x7, e4, e5);
                MMA16816(acc2[1][3], x4, x5, x6, x7, e6, e7);
            }
            __syncthreads();

            if (sc3 == 2) {
#pragma unroll
                for (int n = 0; n < 4; n++) {
                    float v0 = 0.f, v1 = 0.f;
#pragma unroll
                    for (int mi = 0; mi < 2; mi++) {
                        v0 += acc2[mi][n][0] * acc2[mi][n][0] + acc2[mi][n][2] * acc2[mi][n][2];
                        v1 += acc2[mi][n][1] * acc2[mi][n][1] + acc2[mi][n][3] * acc2[mi][n][3];
                    }
#pragma unroll
                    for (int o = 4; o <= 16; o <<= 1) {
                        v0 += __shfl_xor_sync(0xffffffffu, v0, o);
                        v1 += __shfl_xor_sync(0xffffffffu, v1, o);
                    }
                    if (lane < 4) {
                        const int t = (4 * wn2 + n) * 8 + lane * 2;
                        atomicAdd(&wn2A[t], v0);
                        atomicAdd(&wn2A[t + 1], v1);
                    }
                }
            }
        }
    }
    __syncthreads();

    if (tid < 64) {
        const int t = tid;
        float dinv = 1.f / denA[t];
        float wnv = sqrtf(wn2A[t]) * dinv;
        float nm = numA[t] * dinv;
        float qnv = g_qn[ip * 64 + t];
        float cosv = nm / fmaxf(qnv * wnv, EPSf);
        float v = G2f * cosv;
        float m = v;
        for (int o = 16; o; o >>= 1) m = fmaxf(m, __shfl_xor_sync(0xffffffffu, m, o));
        float e = __expf(v - m);
        for (int o = 16; o; o >>= 1) e += __shfl_xor_sync(0xffffffffu, e, o);
        if (lane == 0) g_simT[j * 64 + ip * 2 + (tid >> 5)] = logf(e) + m;
    }
}

// ---------------- moco GEMM: cp.async double-buffered, fused per-block LSE ----------------
__global__ void __launch_bounds__(256) moco_gemm_kernel(const float* __restrict__ queue,
                                                        const float* __restrict__ queue_im) {
    const int k0 = blockIdx.x * 64;
    const int d = blockIdx.y;
    const float* A = g_codes[d];
    const float* Q = (d == 0) ? queue : queue_im;
    __shared__ float sA[2][64 * 36];
    __shared__ float sB[2][32 * 64];
    const int tid = threadIdx.x;
    const int rg = tid >> 4;
    const int kg = tid & 15;
    const uint32_t sbA = smem_u32(sA);
    const uint32_t sbB = smem_u32(sB);
    float acc[4][4];
#pragma unroll
    for (int u = 0; u < 4; u++)
#pragma unroll
        for (int v = 0; v < 4; v++) acc[u][v] = 0.f;

    // prologue: load c-block 0 into buf 0
    for (int idx = tid; idx < 512; idx += 256) {
        int r = idx >> 3, cb = idx & 7;
        cp16(sbA + (r * 36 + cb * 4) * 4, A + r * NEFc + cb * 4);
    }
    for (int idx = tid; idx < 512; idx += 256) {
        int cc = idx >> 4, kk = idx & 15;
        cp16(sbB + (cc * 64 + kk * 4) * 4, Q + (size_t)cc * Kq + k0 + kk * 4);
    }
    CP_COMMIT();

    for (int it = 0; it < 8; it++) {
        const int buf = it & 1;
        if (it + 1 < 8) {
            const int nb = 1 - buf, c0n = (it + 1) * 32;
            for (int idx = tid; idx < 512; idx += 256) {
                int r = idx >> 3, cb = idx & 7;
                cp16(sbA + (nb * 64 * 36 + r * 36 + cb * 4) * 4, A + r * NEFc + c0n + cb * 4);
            }
            for (int idx = tid; idx < 512; idx += 256) {
                int cc = idx >> 4, kk = idx & 15;
                cp16(sbB + (nb * 32 * 64 + cc * 64 + kk * 4) * 4, Q + (size_t)(c0n + cc) * Kq + k0 + kk * 4);
            }
            CP_COMMIT();
            CP_WAIT1();
        } else {
            CP_WAIT0();
        }
        __syncthreads();
#pragma unroll 4
        for (int cc = 0; cc < 32; cc++) {
            float a0 = sA[buf][(rg * 4 + 0) * 36 + cc];
            float a1 = sA[buf][(rg * 4 + 1) * 36 + cc];
            float a2 = sA[buf][(rg * 4 + 2) * 36 + cc];
            float a3 = sA[buf][(rg * 4 + 3) * 36 + cc];
#pragma unroll
            for (int v = 0; v < 4; v++) {
                float b = sB[buf][cc * 64 + kg + 16 * v];
                acc[0][v] += a0 * b;
                acc[1][v] += a1 * b;
                acc[2][v] += a2 * b;
                acc[3][v] += a3 * b;
            }
        }
        __syncthreads();
    }
#pragma unroll
    for (int u = 0; u < 4; u++) {
        float z0 = acc[u][0] * INV_T, z1 = acc[u][1] * INV_T;
        float z2 = acc[u][2] * INV_T, z3 = acc[u][3] * INV_T;
        float m = fmaxf(fmaxf(z0, z1), fmaxf(z2, z3));
        float s = __expf(z0 - m) + __expf(z1 - m) + __expf(z2 - m) + __expf(z3 - m);
#pragma unroll
        for (int o = 1; o < 16; o <<= 1) {
            float om = __shfl_xor_sync(0xffffffffu, m, o);
            float os = __shfl_xor_sync(0xffffffffu, s, o);
            float nm = fmaxf(m, om);
            s = s * __expf(m - nm) + os * __expf(om - nm);
            m = nm;
        }
        if (kg == 0) {
            g_part[d][rg * 4 + u][blockIdx.x][0] = m;
            g_part[d][rg * 4 + u][blockIdx.x][1] = s;
        }
    }
}

// ---------------- pair GEMMs ----------------
#define K5_SMEM ((64 * 257 + 4 * 256) * 4)
__global__ void __launch_bounds__(256) pair_gemm_kernel() {
    const int rb = blockIdx.x, d = blockIdx.y;
    const float* A  = g_codes[(d == 0) ? 0 : 1];
    const float* Bm = g_codes[(d == 0) ? 1 : 3];
    extern __shared__ float sh2[];
    float* shB = sh2;
    float* shA = sh2 + 64 * 257;
    const int tid = threadIdx.x;
    for (int idx = tid; idx < 64 * 256; idx += 256) {
        int r = idx >> 8, c = idx & 255;
        shB[r * 257 + c] = Bm[idx];
    }
    for (int idx = tid; idx < 4 * 256; idx += 256)
        shA[idx] = A[rb * 4 * 256 + idx];
    __syncthreads();
    const int u = tid >> 6, v = tid & 63;
    float s = 0.f;
#pragma unroll 8
    for (int k = 0; k < 256; k++)
        s += shA[u * 256 + k] * shB[v * 257 + k];
    g_small[d][(rb * 4 + u) * 64 + v] = G3f * s;
}

__device__ float lse_md_row(const float* M, int r, float scale) {
    float mx = -FLT_MAX;
    for (int c2 = 0; c2 < 64; c2++) mx = fmaxf(mx, scale * M[r * 64 + c2]);
    float s = 0.f;
    for (int c2 = 0; c2 < 64; c2++) s += __expf(scale * M[r * 64 + c2] - mx);
    return logf(s) + mx - scale * M[r * 64 + r];
}
__device__ float lse_md_col(const float* M, int c2, float scale) {
    float mx = -FLT_MAX;
    for (int r = 0; r < 64; r++) mx = fmaxf(mx, scale * M[r * 64 + c2]);
    float s = 0.f;
    for (int r = 0; r < 64; r++) s += __expf(scale * M[r * 64 + c2] - mx);
    return logf(s) + mx - scale * M[c2 * 64 + c2];
}

__global__ void __launch_bounds__(1024) finalize_kernel(float* __restrict__ out) {
    __shared__ float sv[8][64];
    const int tid = threadIdx.x;
    {
        const int pair = tid >> 3, sub = tid & 7;
        const int d = pair >> 6, i = pair & 63;
        float M = -FLT_MAX, S = 0.f;
        for (int b = sub * 32; b < sub * 32 + 32; b++) {
            float m = g_part[d][i][b][0], s = g_part[d][i][b][1];
            float nm = fmaxf(M, m);
            S = S * __expf(M - nm) + s * __expf(m - nm);
            M = nm;
        }
#pragma unroll
        for (int o = 1; o < 8; o <<= 1) {
            float oM = __shfl_xor_sync(0xffffffffu, M, o);
            float oS = __shfl_xor_sync(0xffffffffu, S, o);
            float nm = fmaxf(M, oM);
            S = S * __expf(M - nm) + oS * __expf(oM - nm);
            M = nm;
        }
        if (sub == 0) {
            float pos = 0.f;
            const float* a = g_codes[d];
            const float* b2 = g_codes[(d == 0) ? 3 : 2];
            for (int k = 0; k < NEFc; k++) pos += a[i * NEFc + k] * b2[i * NEFc + k];
            pos *= INV_T;
            float Mf = fmaxf(pos, M);
            float Sf = __expf(pos - Mf) + S * __expf(M - Mf);
            sv[6 + d][i] = logf(Sf) + Mf - pos;
        }
    }
    if (tid < 384) {
        const int kind = tid >> 6, i = tid & 63;
        float r;
        switch (kind) {
            case 0: r = lse_md_row(g_simT, i, G3f); break;
            case 1: r = lse_md_col(g_simT, i, G3f); break;
            case 2: r = lse_md_row(g_small[0], i, 1.f); break;
            case 3: r = lse_md_col(g_small[0], i, 1.f); break;
            case 4: r = lse_md_row(g_small[1], i, 1.f); break;
            default: r = lse_md_col(g_small[1], i, 1.f); break;
        }
        sv[(kind < 5) ? kind : 5][i] = r;
    }
    __syncthreads();
    if (tid == 0) {
        float a[8];
        for (int q2 = 0; q2 < 8; q2++) {
            float s = 0.f;
            for (int k = 0; k < 64; k++) s += sv[q2][k];
            a[q2] = s * (1.f / 64.f);
        }
        out[0] = a[0];
        out[1] = a[1];
        out[2] = a[2];
        out[3] = a[3];
        out[4] = 0.5f * (a[6] + a[7]);
        out[5] = a[4];
        out[6] = a[5];
    }
}

extern "C" void kernel_launch(void* const* d_in, const int* in_sizes, int n_in,
                              void* d_out, int out_size) {
    const float* cnn      = (const float*)d_in[0];
    const float* rnn      = (const float*)d_in[1];
    const float* imgf     = (const float*)d_in[2];
    const float* we       = (const float*)d_in[3];
    const float* cnn_aug  = (const float*)d_in[4];
    const float* rnn_aug  = (const float*)d_in[5];
    const float* queue    = (const float*)d_in[6];
    const float* queue_im = (const float*)d_in[7];
    float* out = (float*)d_out;

    cudaFuncSetAttribute(prep_AX, cudaFuncAttributeMaxDynamicSharedMemorySize, PAX_SMEM);
    cudaFuncSetAttribute(word_mma_kernel, cudaFuncAttributeMaxDynamicSharedMemorySize, WK_SMEM);
    cudaFuncSetAttribute(pair_gemm_kernel, cudaFuncAttributeMaxDynamicSharedMemorySize, K5_SMEM);

    prep_B<<<2048, 256>>>(we);                                           // 1
    normalize_kernel<<<dim3(64, 4), 256>>>(cnn, rnn, cnn_aug, rnn_aug);  // 2
    moco_gemm_kernel<<<dim3(256, 2), 256>>>(queue, queue_im);            // 3
    prep_AX<<<dim3(64, 4), 256, PAX_SMEM>>>(imgf);                       // 4  <- ncu capture slot
    word_mma_kernel<<<2048, 256, WK_SMEM>>>();                           // 5
    pair_gemm_kernel<<<dim3(16, 2), 256, K5_SMEM>>>();                   // 6
    finalize_kernel<<<1, 1024>>>(out);                                   // 7
}

// round 16
// speedup vs baseline: 1.3046x; 1.0193x over previous
#include <cuda_runtime.h>
#include <cuda_bf16.h>
#include <math.h>
#include <float.h>
#include <stdint.h>

#define Bn   64
#define Tn   32
#define NEFc 256
#define Sn   289
#define SPAD 384
#define S2   304
#define Kq   16384
#define G1f  4.0f
#define G2f  5.0f
#define G3f  10.0f
#define INV_T 20.0f
#define EPSf 1e-8f

// ---------------- device scratch (bf16 single precision copies) ----------------
__device__ uint4 g_A4[64 * SPAD * 256 / 8];   // ctxT [j][s_pad][c] bf16
__device__ uint4 g_X4[64 * 256 * SPAD / 8];   // imgf [j][c][s_pad] bf16
__device__ uint4 g_B4[2048 * 256 / 8];        // we   [i*32+t][c] bf16
__device__ float g_qn[2048];
__device__ float g_codes[4][Bn * NEFc];
__device__ float g_simT[Bn * Bn];
__device__ float g_part[2][Bn][256][2];       // moco per-kblock (max, sumexp)
__device__ float g_small[2][Bn * Bn];

// ---------------- helpers ----------------
__device__ __forceinline__ uint32_t smem_u32(const void* p) {
    uint32_t a;
    asm("{ .reg .u64 t; cvta.to.shared.u64 t, %1; cvt.u32.u64 %0, t; }" : "=r"(a) : "l"(p));
    return a;
}
__device__ __forceinline__ void ldm_x4(uint32_t addr, uint32_t& r0, uint32_t& r1, uint32_t& r2, uint32_t& r3) {
    asm volatile("ldmatrix.sync.aligned.m8n8.x4.shared.b16 {%0,%1,%2,%3}, [%4];"
                 : "=r"(r0), "=r"(r1), "=r"(r2), "=r"(r3) : "r"(addr));
}
#define MMA16816(d, A0, A1, A2, A3, B0, B1)                                   \
    asm volatile("mma.sync.aligned.m16n8k16.row.col.f32.bf16.bf16.f32 "       \
                 "{%0,%1,%2,%3},{%4,%5,%6,%7},{%8,%9},{%0,%1,%2,%3};"          \
                 : "+f"((d)[0]), "+f"((d)[1]), "+f"((d)[2]), "+f"((d)[3])      \
                 : "r"(A0), "r"(A1), "r"(A2), "r"(A3), "r"(B0), "r"(B1))

__device__ __forceinline__ void cp16(uint32_t s, const void* g) {
    asm volatile("cp.async.ca.shared.global [%0], [%1], 16;" :: "r"(s), "l"(g));
}
#define CP_COMMIT() asm volatile("cp.async.commit_group;" ::: "memory")
#define CP_WAIT0()  asm volatile("cp.async.wait_group 0;" ::: "memory")
#define CP_WAIT1()  asm volatile("cp.async.wait_group 1;" ::: "memory")

// ---------------- prep_AX (vectorized, 512 thr) ----------------
#define PAX_SMEM (64 * 385 * 4)
__global__ void __launch_bounds__(512) prep_AX(const float* __restrict__ imgf) {
    const int j = blockIdx.x, ct = blockIdx.y;
    extern __shared__ float tile[];
    const int tid = threadIdx.x;
    const float4* src4 = (const float4*)(imgf + ((size_t)j * 256 + ct * 64) * Sn);
    for (int idx = tid; idx < 4624; idx += 512) {
        float4 v = src4[idx];
        int f = idx * 4;
        int r0 = f / Sn, s0 = f - r0 * Sn;
        tile[r0 * 385 + s0] = v.x;
        int f1 = f + 1; int r1 = f1 / Sn, s1 = f1 - r1 * Sn;
        tile[r1 * 385 + s1] = v.y;
        int f2 = f + 2; int r2 = f2 / Sn, s2 = f2 - r2 * Sn;
        tile[r2 * 385 + s2] = v.z;
        int f3 = f + 3; int r3 = f3 / Sn, s3 = f3 - r3 * Sn;
        tile[r3 * 385 + s3] = v.w;
    }
    __syncthreads();
    for (int idx = tid; idx < SPAD * 8; idx += 512) {
        const int s = idx >> 3, cg = idx & 7;
        uint4 o;
        __nv_bfloat16* ob = (__nv_bfloat16*)&o;
#pragma unroll
        for (int u = 0; u < 8; u++) {
            float v = (s < Sn) ? tile[(cg * 8 + u) * 385 + s] : 0.f;
            ob[u] = __float2bfloat16(v);
        }
        *(uint4*)(((__nv_bfloat16*)g_A4) + ((size_t)j * SPAD + s) * 256 + ct * 64 + cg * 8) = o;
    }
    for (int idx = tid; idx < 64 * 38; idx += 512) {
        const int c = idx / 38, sg = idx - c * 38;
        const int s0 = sg * 8;
        uint4 o;
        __nv_bfloat16* ob = (__nv_bfloat16*)&o;
#pragma unroll
        for (int u = 0; u < 8; u++) {
            int s = s0 + u;
            float v = (s < Sn) ? tile[c * 385 + s] : 0.f;
            ob[u] = __float2bfloat16(v);
        }
        *(uint4*)(((__nv_bfloat16*)g_X4) + ((size_t)j * 256 + ct * 64 + c) * SPAD + s0) = o;
    }
}

// ---------------- prep_B + normalize merged ----------------
__global__ void prep_BN(const float* __restrict__ we,
                        const float* __restrict__ c0, const float* __restrict__ c1,
                        const float* __restrict__ c2, const float* __restrict__ c3) {
    const int bid = blockIdx.x;
    const int tid = threadIdx.x;
    __shared__ float red[8];
    if (bid < 2048) {
        const int r = bid, c = tid;
        float v = we[(size_t)r * 256 + c];
        ((__nv_bfloat16*)g_B4)[(size_t)r * 256 + c] = __float2bfloat16(v);
        float s = v * v;
        for (int o = 16; o; o >>= 1) s += __shfl_down_sync(0xffffffffu, s, o);
        if ((c & 31) == 0) red[c >> 5] = s;
        __syncthreads();
        if (c == 0) {
            float tot = 0.f;
#pragma unroll
            for (int w = 0; w < 8; w++) tot += red[w];
            g_qn[r] = sqrtf(tot);
        }
    } else {
        const int r = bid - 2048;
        const int i = r & 63, m = r >> 6;
        const float* src = (m == 0) ? c0 : (m == 1) ? c1 : (m == 2) ? c2 : c3;
        float v = src[i * NEFc + tid];
        float s = v * v;
        for (int o = 16; o; o >>= 1) s += __shfl_down_sync(0xffffffffu, s, o);
        if ((tid & 31) == 0) red[tid >> 5] = s;
        __syncthreads();
        float tot = 0.f;
#pragma unroll
        for (int w = 0; w < 8; w++) tot += red[w];
        g_codes[m][i * NEFc + tid] = v / fmaxf(sqrtf(tot), EPSf);
    }
}

// ---------------- word kernel smem layout (bytes) ----------------
#define OFF_SC   0
#define OFF_W    83200
#define OFF_AB   116992
#define OFF_XW   83200
#define OFF_E    118016
#define OFF_XB0  0
#define OFF_XB1  34816
#define OFF_DEN  184576
#define OFF_NUM  184832
#define OFF_WN2  185088
#define OFF_RMAX 185344
#define OFF_RINV 187904
#define WK_SMEM  190464

__global__ void __launch_bounds__(256, 1) word_mma_kernel() {
    const int j  = blockIdx.x >> 5;
    const int ip = blockIdx.x & 31;
    extern __shared__ char sm[];
    const uint32_t sb = smem_u32(sm);
    const int tid = threadIdx.x, lane = tid & 31, w = tid >> 5;

    float* scp   = (float*)(sm + OFF_SC);
    float* denA  = (float*)(sm + OFF_DEN);
    float* numA  = (float*)(sm + OFF_NUM);
    float* wn2A  = (float*)(sm + OFF_WN2);
    float* rmaxp = (float*)(sm + OFF_RMAX);
    float* rinvp = (float*)(sm + OFF_RINV);
    if (tid < 192) denA[tid] = 0.f;

    for (int idx = tid; idx < 2048; idx += 256) {
        int r = idx >> 5, cb = idx & 31;
        cp16(sb + OFF_W + r * 528 + cb * 16, g_B4 + (((size_t)(ip * 64 + r)) << 5) + cb);
    }
    for (int idx = tid; idx < 4096; idx += 256) {
        int r = idx >> 5, cb = idx & 31;
        cp16(sb + OFF_AB + r * 528 + cb * 16, g_A4 + (((size_t)j * SPAD + r) << 5) + cb);
    }
    CP_COMMIT();

    const uint32_t rowA  = (lane & 7) + ((lane >> 3) & 1) * 8;
    const uint32_t coffA = (lane >> 4) * 16;
    const uint32_t boffB = ((lane >> 3) & 1) * 16;

    // ===== phase 1a =====
    {
        const int wm = w >> 1;
        const int wn = w & 1;
        const uint32_t bRow = 32u * wn + (((uint32_t)lane >> 4) << 3) + (lane & 7);
        const uint32_t bB = sb + OFF_W + bRow * 528 + boffB;

        for (int ch = 0; ch < 2; ch++) {
            CP_WAIT0();
            __syncthreads();

            float acc[2][4][4];
#pragma unroll
            for (int mi = 0; mi < 2; mi++)
#pragma unroll
                for (int nf = 0; nf < 4; nf++)
#pragma unroll
                    for (int r = 0; r < 4; r++) acc[mi][nf][r] = 0.f;

            const uint32_t aB = sb + OFF_AB + (wm * 32 + rowA) * 528 + coffA;

#pragma unroll 4
            for (int k = 0; k < 16; k++) {
                const uint32_t kb = (uint32_t)k * 32u;
                uint32_t a0, a1, a2, a3, a4, a5, a6, a7;
                uint32_t h0, h1, h2, h3, h4, h5, h6, h7;
                ldm_x4(aB + kb, a0, a1, a2, a3);
                ldm_x4(aB + 16 * 528 + kb, a4, a5, a6, a7);
                ldm_x4(bB + kb, h0, h1, h2, h3);
                ldm_x4(bB + 16 * 528 + kb, h4, h5, h6, h7);
                MMA16816(acc[0][0], a0, a1, a2, a3, h0, h1);
                MMA16816(acc[0][1], a0, a1, a2, a3, h2, h3);
                MMA16816(acc[0][2], a0, a1, a2, a3, h4, h5);
                MMA16816(acc[0][3], a0, a1, a2, a3, h6, h7);
                MMA16816(acc[1][0], a4, a5, a6, a7, h0, h1);
                MMA16816(acc[1][1], a4, a5, a6, a7, h2, h3);
                MMA16816(acc[1][2], a4, a5, a6, a7, h4, h5);
                MMA16816(acc[1][3], a4, a5, a6, a7, h6, h7);
            }
            __syncthreads();

            if (ch == 0) {
                for (int idx = tid; idx < 4096; idx += 256) {
                    int r = idx >> 5, cb = idx & 31;
                    cp16(sb + OFF_AB + r * 528 + cb * 16,
                         g_A4 + (((size_t)j * SPAD + 128 + r) << 5) + cb);
                }
                CP_COMMIT();
            } else {
                for (int idx = tid; idx < 2048; idx += 256) {
                    int r = idx >> 5, cb = idx & 31;
                    cp16(sb + OFF_AB + r * 528 + cb * 16,
                         g_A4 + (((size_t)j * SPAD + 256 + r) << 5) + cb);
                }
                CP_COMMIT();
            }

#pragma unroll
            for (int mi = 0; mi < 2; mi++) {
                const int row = ch * 128 + wm * 32 + mi * 16 + (lane >> 2);
#pragma unroll
                for (int nf = 0; nf < 4; nf++) {
                    const int col = wn * 32 + nf * 8 + (lane & 3) * 2;
                    scp[row * 65 + col]           = acc[mi][nf][0];
                    scp[row * 65 + col + 1]       = acc[mi][nf][1];
                    scp[(row + 8) * 65 + col]     = acc[mi][nf][2];
                    scp[(row + 8) * 65 + col + 1] = acc[mi][nf][3];
                }
            }
        }
    }

    // ===== phase 1b: tail =====
    {
        const int wk  = w >> 2;
        const int wm1 = (w >> 1) & 1;
        const int wn1 = w & 1;
        const uint32_t bRow1 = 32u * wn1 + (((uint32_t)lane >> 4) << 3) + (lane & 7);

        CP_WAIT0();
        __syncthreads();

        float acc[2][4][4];
#pragma unroll
        for (int mi = 0; mi < 2; mi++)
#pragma unroll
            for (int nf = 0; nf < 4; nf++)
#pragma unroll
                for (int r = 0; r < 4; r++) acc[mi][nf][r] = 0.f;

        const uint32_t aB = sb + OFF_AB + (wm1 * 32 + rowA) * 528 + coffA + (uint32_t)wk * 256u;
        const uint32_t bB = sb + OFF_W + bRow1 * 528 + boffB + (uint32_t)wk * 256u;

#pragma unroll
        for (int k = 0; k < 8; k++) {
            const uint32_t kb = (uint32_t)k * 32u;
            uint32_t a0, a1, a2, a3, a4, a5, a6, a7;
            uint32_t h0, h1, h2, h3, h4, h5, h6, h7;
            ldm_x4(aB + kb, a0, a1, a2, a3);
            ldm_x4(aB + 16 * 528 + kb, a4, a5, a6, a7);
            ldm_x4(bB + kb, h0, h1, h2, h3);
            ldm_x4(bB + 16 * 528 + kb, h4, h5, h6, h7);
            MMA16816(acc[0][0], a0, a1, a2, a3, h0, h1);
            MMA16816(acc[0][1], a0, a1, a2, a3, h2, h3);
            MMA16816(acc[0][2], a0, a1, a2, a3, h4, h5);
            MMA16816(acc[0][3], a0, a1, a2, a3, h6, h7);
            MMA16816(acc[1][0], a4, a5, a6, a7, h0, h1);
            MMA16816(acc[1][1], a4, a5, a6, a7, h2, h3);
            MMA16816(acc[1][2], a4, a5, a6, a7, h4, h5);
            MMA16816(acc[1][3], a4, a5, a6, a7, h6, h7);
        }

        if (wk == 0) {
#pragma unroll
            for (int mi = 0; mi < 2; mi++) {
                const int row = 256 + wm1 * 32 + mi * 16 + (lane >> 2);
#pragma unroll
                for (int nf = 0; nf < 4; nf++) {
                    const int col = wn1 * 32 + nf * 8 + (lane & 3) * 2;
                    scp[row * 65 + col]           = acc[mi][nf][0];
                    scp[row * 65 + col + 1]       = acc[mi][nf][1];
                    scp[(row + 8) * 65 + col]     = acc[mi][nf][2];
                    scp[(row + 8) * 65 + col + 1] = acc[mi][nf][3];
                }
            }
        }
        __syncthreads();

        for (int idx = tid; idx < 2048; idx += 256) {
            int r = idx >> 4, cb = idx & 15;
            cp16(sb + OFF_XW + r * 272 + cb * 16, g_X4 + (((size_t)(j * 256 + r)) * 48) + cb);
        }
        CP_COMMIT();

        if (wk == 1) {
#pragma unroll
            for (int mi = 0; mi < 2; mi++) {
                const int row = 256 + wm1 * 32 + mi * 16 + (lane >> 2);
#pragma unroll
                for (int nf = 0; nf < 4; nf++) {
                    const int col = wn1 * 32 + nf * 8 + (lane & 3) * 2;
                    scp[row * 65 + col]           += acc[mi][nf][0];
                    scp[row * 65 + col + 1]       += acc[mi][nf][1];
                    scp[(row + 8) * 65 + col]     += acc[mi][nf][2];
                    scp[(row + 8) * 65 + col + 1] += acc[mi][nf][3];
                }
            }
        }
    }
    __syncthreads();

    // ===== epilogue =====
    for (int r = tid; r < 320; r += 256) {
#pragma unroll
        for (int h = 0; h < 2; h++) {
            float m = -FLT_MAX;
            for (int t = 0; t < 32; t++) m = fmaxf(m, scp[r * 65 + h * 32 + t]);
            float s = 0.f;
            for (int t = 0; t < 32; t++) s += __expf(scp[r * 65 + h * 32 + t] - m);
            rmaxp[r * 2 + h] = m;
            rinvp[r * 2 + h] = 1.f / s;
        }
    }
    __syncthreads();
    {
        const int t = tid & 63, sg = tid >> 6, h = t >> 5;
        float dpart = 0.f, npart = 0.f;
        __nv_bfloat16* eP = (__nv_bfloat16*)(sm + OFF_E);
        for (int k2 = 0; k2 < 76; k2++) {
            const int s = sg * 76 + k2;
            float e = 0.f;
            if (s < Sn) {
                float sv = scp[s * 65 + t];
                float a1 = __expf(sv - rmaxp[s * 2 + h]) * rinvp[s * 2 + h];
                e = __expf(G1f * a1);
                dpart += e;
                npart += e * sv;
            }
            eP[t * 392 + s] = __float2bfloat16(e);
        }
        atomicAdd(&denA[t], dpart);
        atomicAdd(&numA[t], npart);
    }
    __syncthreads();

    // ===== phase 2 =====
    {
        const int wm2 = w >> 1;
        const int wn2 = w & 1;
        const uint32_t bRow2 = 32u * wn2 + (((uint32_t)lane >> 4) << 3) + (lane & 7);

        float acc2[2][4][4];
        for (int q = 0; q < 6; q++) {
            const int sc3 = q % 3;
            const uint32_t xb = (q == 0) ? (sb + OFF_XW)
                              : (sb + ((q & 1) ? OFF_XB0 : OFF_XB1));
            if (q + 1 < 6) {
                const int mtn = (q + 1) / 3, sc3n = (q + 1) % 3;
                uint32_t dst = sb + (((q + 1) & 1) ? OFF_XB0 : OFF_XB1);
                if (sc3n < 2) {
                    for (int idx = tid; idx < 2048; idx += 256) {
                        int r = idx >> 4, cb = idx & 15;
                        cp16(dst + r * 272 + cb * 16,
                             g_X4 + (((size_t)(j * 256 + mtn * 128 + r)) * 48) + sc3n * 16 + cb);
                    }
                } else {
                    for (int idx = tid; idx < 768; idx += 256) {
                        int r = idx / 6, cb = idx % 6;
                        cp16(dst + r * 272 + cb * 16,
                             g_X4 + (((size_t)(j * 256 + mtn * 128 + r)) * 48) + 32 + cb);
                    }
                }
                CP_COMMIT();
                CP_WAIT1();
            } else {
                CP_WAIT0();
            }
            __syncthreads();

            if (sc3 == 0) {
#pragma unroll
                for (int mi = 0; mi < 2; mi++)
#pragma unroll
                    for (int n = 0; n < 4; n++)
#pragma unroll
                        for (int r = 0; r < 4; r++) acc2[mi][n][r] = 0.f;
            }

            const uint32_t eB0 = sb + OFF_E + bRow2 * 784 + (uint32_t)sc3 * 256u + boffB;
            const uint32_t eB1 = eB0 + 16 * 784;
            const uint32_t xA  = xb + (wm2 * 32 + rowA) * 272 + coffA;

            const int kmax = (sc3 == 2) ? 3 : 8;
#pragma unroll 4
            for (int k = 0; k < kmax; k++) {
                const uint32_t kb = (uint32_t)k * 32u;
                uint32_t x0, x1, x2, x3, x4, x5, x6, x7;
                uint32_t e0, e1, e2, e3, e4, e5, e6, e7;
                ldm_x4(xA + kb, x0, x1, x2, x3);
                ldm_x4(xA + 16 * 272 + kb, x4, x5, x6, x7);
                ldm_x4(eB0 + kb, e0, e1, e2, e3);
                ldm_x4(eB1 + kb, e4, e5, e6, e7);
                MMA16816(acc2[0][0], x0, x1, x2, x3, e0, e1);
                MMA16816(acc2[0][1], x0, x1, x2, x3, e2, e3);
                MMA16816(acc2[0][2], x0, x1, x2, x3, e4, e5);
                MMA16816(acc2[0][3], x0, x1, x2, x3, e6, e7);
                MMA16816(acc2[1][0], x4, x5, x6, x7, e0, e1);
                MMA16816(acc2[1][1], x4, x5, x6, x7, e2, e3);
                MMA16816(acc2[1][2], x4, x5, x6, x7, e4, e5);
                MMA16816(acc2[1][3], x4, x5, x6, x7, e6, e7);
            }
            __syncthreads();

            if (sc3 == 2) {
#pragma unroll
                for (int n = 0; n < 4; n++) {
                    float v0 = 0.f, v1 = 0.f;
#pragma unroll
                    for (int mi = 0; mi < 2; mi++) {
                        v0 += acc2[mi][n][0] * acc2[mi][n][0] + acc2[mi][n][2] * acc2[mi][n][2];
                        v1 += acc2[mi][n][1] * acc2[mi][n][1] + acc2[mi][n][3] * acc2[mi][n][3];
                    }
#pragma unroll
                    for (int o = 4; o <= 16; o <<= 1) {
                        v0 += __shfl_xor_sync(0xffffffffu, v0, o);
                        v1 += __shfl_xor_sync(0xffffffffu, v1, o);
                    }
                    if (lane < 4) {
                        const int t = (4 * wn2 + n) * 8 + lane * 2;
                        atomicAdd(&wn2A[t], v0);
                        atomicAdd(&wn2A[t + 1], v1);
                    }
                }
            }
        }
    }
    __syncthreads();

    if (tid < 64) {
        const int t = tid;
        float dinv = 1.f / denA[t];
        float wnv = sqrtf(wn2A[t]) * dinv;
        float nm = numA[t] * dinv;
        float qnv = g_qn[ip * 64 + t];
        float cosv = nm / fmaxf(qnv * wnv, EPSf);
        float v = G2f * cosv;
        float m = v;
        for (int o = 16; o; o >>= 1) m = fmaxf(m, __shfl_xor_sync(0xffffffffu, m, o));
        float e = __expf(v - m);
        for (int o = 16; o; o >>= 1) e += __shfl_xor_sync(0xffffffffu, e, o);
        if (lane == 0) g_simT[j * 64 + ip * 2 + (tid >> 5)] = logf(e) + m;
    }
}

// ---------------- moco GEMM: cp.async double-buffered, fused per-block LSE ----------------
__global__ void __launch_bounds__(256) moco_gemm_kernel(const float* __restrict__ queue,
                                                        const float* __restrict__ queue_im) {
    const int k0 = blockIdx.x * 64;
    const int d = blockIdx.y;
    const float* A = g_codes[d];
    const float* Q = (d == 0) ? queue : queue_im;
    __shared__ float sA[2][64 * 36];
    __shared__ float sB[2][32 * 64];
    const int tid = threadIdx.x;
    const int rg = tid >> 4;
    const int kg = tid & 15;
    const uint32_t sbA = smem_u32(sA);
    const uint32_t sbB = smem_u32(sB);
    float acc[4][4];
#pragma unroll
    for (int u = 0; u < 4; u++)
#pragma unroll
        for (int v = 0; v < 4; v++) acc[u][v] = 0.f;

    for (int idx = tid; idx < 512; idx += 256) {
        int r = idx >> 3, cb = idx & 7;
        cp16(sbA + (r * 36 + cb * 4) * 4, A + r * NEFc + cb * 4);
    }
    for (int idx = tid; idx < 512; idx += 256) {
        int cc = idx >> 4, kk = idx & 15;
        cp16(sbB + (cc * 64 + kk * 4) * 4, Q + (size_t)cc * Kq + k0 + kk * 4);
    }
    CP_COMMIT();

    for (int it = 0; it < 8; it++) {
        const int buf = it & 1;
        if (it + 1 < 8) {
            const int nb = 1 - buf, c0n = (it + 1) * 32;
            for (int idx = tid; idx < 512; idx += 256) {
                int r = idx >> 3, cb = idx & 7;
                cp16(sbA + (nb * 64 * 36 + r * 36 + cb * 4) * 4, A + r * NEFc + c0n + cb * 4);
            }
            for (int idx = tid; idx < 512; idx += 256) {
                int cc = idx >> 4, kk = idx & 15;
                cp16(sbB + (nb * 32 * 64 + cc * 64 + kk * 4) * 4, Q + (size_t)(c0n + cc) * Kq + k0 + kk * 4);
            }
            CP_COMMIT();
            CP_WAIT1();
        } else {
            CP_WAIT0();
        }
        __syncthreads();
#pragma unroll 4
        for (int cc = 0; cc < 32; cc++) {
            float a0 = sA[buf][(rg * 4 + 0) * 36 + cc];
            float a1 = sA[buf][(rg * 4 + 1) * 36 + cc];
            float a2 = sA[buf][(rg * 4 + 2) * 36 + cc];
            float a3 = sA[buf][(rg * 4 + 3) * 36 + cc];
#pragma unroll
            for (int v = 0; v < 4; v++) {
                float b = sB[buf][cc * 64 + kg + 16 * v];
                acc[0][v] += a0 * b;
                acc[1][v] += a1 * b;
                acc[2][v] += a2 * b;
                acc[3][v] += a3 * b;
            }
        }
        __syncthreads();
    }
#pragma unroll
    for (int u = 0; u < 4; u++) {
        float z0 = acc[u][0] * INV_T, z1 = acc[u][1] * INV_T;
        float z2 = acc[u][2] * INV_T, z3 = acc[u][3] * INV_T;
        float m = fmaxf(fmaxf(z0, z1), fmaxf(z2, z3));
        float s = __expf(z0 - m) + __expf(z1 - m) + __expf(z2 - m) + __expf(z3 - m);
#pragma unroll
        for (int o = 1; o < 16; o <<= 1) {
            float om = __shfl_xor_sync(0xffffffffu, m, o);
            float os = __shfl_xor_sync(0xffffffffu, s, o);
            float nm = fmaxf(m, om);
            s = s * __expf(m - nm) + os * __expf(om - nm);
            m = nm;
        }
        if (kg == 0) {
            g_part[d][rg * 4 + u][blockIdx.x][0] = m;
            g_part[d][rg * 4 + u][blockIdx.x][1] = s;
        }
    }
}

// ---------------- pair GEMMs ----------------
#define K5_SMEM ((64 * 257 + 4 * 256) * 4)
__global__ void __launch_bounds__(256) pair_gemm_kernel() {
    const int rb = blockIdx.x, d = blockIdx.y;
    const float* A  = g_codes[(d == 0) ? 0 : 1];
    const float* Bm = g_codes[(d == 0) ? 1 : 3];
    extern __shared__ float sh2[];
    float* shB = sh2;
    float* shA = sh2 + 64 * 257;
    const int tid = threadIdx.x;
    for (int idx = tid; idx < 64 * 256; idx += 256) {
        int r = idx >> 8, c = idx & 255;
        shB[r * 257 + c] = Bm[idx];
    }
    for (int idx = tid; idx < 4 * 256; idx += 256)
        shA[idx] = A[rb * 4 * 256 + idx];
    __syncthreads();
    const int u = tid >> 6, v = tid & 63;
    float s = 0.f;
#pragma unroll 8
    for (int k = 0; k < 256; k++)
        s += shA[u * 256 + k] * shB[v * 257 + k];
    g_small[d][(rb * 4 + u) * 64 + v] = G3f * s;
}

__device__ float lse_md_row(const float* M, int r, float scale) {
    float mx = -FLT_MAX;
    for (int c2 = 0; c2 < 64; c2++) mx = fmaxf(mx, scale * M[r * 64 + c2]);
    float s = 0.f;
    for (int c2 = 0; c2 < 64; c2++) s += __expf(scale * M[r * 64 + c2] - mx);
    return logf(s) + mx - scale * M[r * 64 + r];
}
__device__ float lse_md_col(const float* M, int c2, float scale) {
    float mx = -FLT_MAX;
    for (int r = 0; r < 64; r++) mx = fmaxf(mx, scale * M[r * 64 + c2]);
    float s = 0.f;
    for (int r = 0; r < 64; r++) s += __expf(scale * M[r * 64 + c2] - mx);
    return logf(s) + mx - scale * M[c2 * 64 + c2];
}

__global__ void __launch_bounds__(1024) finalize_kernel(float* __restrict__ out) {
    __shared__ float sv[8][64];
    const int tid = threadIdx.x;
    {
        const int pair = tid >> 3, sub = tid & 7;
        const int d = pair >> 6, i = pair & 63;
        float M = -FLT_MAX, S = 0.f;
        for (int b = sub * 32; b < sub * 32 + 32; b++) {
            float m = g_part[d][i][b][0], s = g_part[d][i][b][1];
            float nm = fmaxf(M, m);
            S = S * __expf(M - nm) + s * __expf(m - nm);
            M = nm;
        }
#pragma unroll
        for (int o = 1; o < 8; o <<= 1) {
            float oM = __shfl_xor_sync(0xffffffffu, M, o);
            float oS = __shfl_xor_sync(0xffffffffu, S, o);
            float nm = fmaxf(M, oM);
            S = S * __expf(M - nm) + oS * __expf(oM - nm);
            M = nm;
        }
        if (sub == 0) {
            float pos = 0.f;
            const float* a = g_codes[d];
            const float* b2 = g_codes[(d == 0) ? 3 : 2];
            for (int k = 0; k < NEFc; k++) pos += a[i * NEFc + k] * b2[i * NEFc + k];
            pos *= INV_T;
            float Mf = fmaxf(pos, M);
            float Sf = __expf(pos - Mf) + S * __expf(M - Mf);
            sv[6 + d][i] = logf(Sf) + Mf - pos;
        }
    }
    if (tid < 384) {
        const int kind = tid >> 6, i = tid & 63;
        float r;
        switch (kind) {
            case 0: r = lse_md_row(g_simT, i, G3f); break;
            case 1: r = lse_md_col(g_simT, i, G3f); break;
            case 2: r = lse_md_row(g_small[0], i, 1.f); break;
            case 3: r = lse_md_col(g_small[0], i, 1.f); break;
            case 4: r = lse_md_row(g_small[1], i, 1.f); break;
            default: r = lse_md_col(g_small[1], i, 1.f); break;
        }
        sv[(kind < 5) ? kind : 5][i] = r;
    }
    __syncthreads();
    if (tid == 0) {
        float a[8];
        for (int q2 = 0; q2 < 8; q2++) {
            float s = 0.f;
            for (int k = 0; k < 64; k++) s += sv[q2][k];
            a[q2] = s * (1.f / 64.f);
        }
        out[0] = a[0];
        out[1] = a[1];
        out[2] = a[2];
        out[3] = a[3];
        out[4] = 0.5f * (a[6] + a[7]);
        out[5] = a[4];
        out[6] = a[5];
    }
}

extern "C" void kernel_launch(void* const* d_in, const int* in_sizes, int n_in,
                              void* d_out, int out_size) {
    const float* cnn      = (const float*)d_in[0];
    const float* rnn      = (const float*)d_in[1];
    const float* imgf     = (const float*)d_in[2];
    const float* we       = (const float*)d_in[3];
    const float* cnn_aug  = (const float*)d_in[4];
    const float* rnn_aug  = (const float*)d_in[5];
    const float* queue    = (const float*)d_in[6];
    const float* queue_im = (const float*)d_in[7];
    float* out = (float*)d_out;

    cudaFuncSetAttribute(prep_AX, cudaFuncAttributeMaxDynamicSharedMemorySize, PAX_SMEM);
    cudaFuncSetAttribute(word_mma_kernel, cudaFuncAttributeMaxDynamicSharedMemorySize, WK_SMEM);
    cudaFuncSetAttribute(pair_gemm_kernel, cudaFuncAttributeMaxDynamicSharedMemorySize, K5_SMEM);

    prep_BN<<<2304, 256>>>(we, cnn, rnn, cnn_aug, rnn_aug);              // 1
    prep_AX<<<dim3(64, 4), 512, PAX_SMEM>>>(imgf);                       // 2
    pair_gemm_kernel<<<dim3(16, 2), 256, K5_SMEM>>>();                   // 3
    moco_gemm_kernel<<<dim3(256, 2), 256>>>(queue, queue_im);            // 4  <- ncu capture slot
    word_mma_kernel<<<2048, 256, WK_SMEM>>>();                           // 5
    finalize_kernel<<<1, 1024>>>(out);                                   // 6
}